// round 1
// baseline (speedup 1.0000x reference)
#include <cuda_runtime.h>
#include <cuda_bf16.h>
#include <cstdint>

// ---------------------------------------------------------------------------
// GCN encoder: N=50000, E=500000, 128 -> 256 -> 512 -> 128
// agg-first formulation: layer_k = BNReLU( (A x_in) @ W + b )
// ---------------------------------------------------------------------------

#define MAXN 50048
#define EPS 1e-5f

__device__ float g_deg[MAXN];                 // degree -> dinv (in place)
__device__ float g_agg1[(size_t)MAXN * 128];
__device__ float g_h1[(size_t)MAXN * 256];
__device__ float g_agg2[(size_t)MAXN * 256];
__device__ float g_h2[(size_t)MAXN * 512];
__device__ float g_sums[512];
__device__ float g_sumsq[512];
__device__ int   g_flag32;                    // 1 => edge_index is int32

// ---------------------------------------------------------------------------

__device__ __forceinline__ void red_add_v4(float* addr, float4 v) {
    asm volatile("red.global.add.v4.f32 [%0], {%1,%2,%3,%4};"
                 :: "l"(addr), "f"(v.x), "f"(v.y), "f"(v.z), "f"(v.w)
                 : "memory");
}

__device__ __forceinline__ int load_idx(const void* ei, long long pos, int is32) {
    if (is32) return ((const int*)ei)[pos];
    return (int)(((const long long*)ei)[pos]);
}

// --- init: deg = 1 (self loop), flag = 0 ----------------------------------
__global__ void k_init(float* deg, int n, int* flag) {
    int i = blockIdx.x * blockDim.x + threadIdx.x;
    if (i < n) deg[i] = 1.0f;
    if (i == 0) *flag = 0;
}

// --- detect int32 vs int64: odd 32-bit words all zero <=> int64 -----------
__global__ void k_detect(const int* ei32, long long E, int* flag) {
    long long i = blockIdx.x * (long long)blockDim.x + threadIdx.x;
    long long stride = (long long)gridDim.x * blockDim.x;
    int any = 0;
    for (; i < E; i += stride)
        if (ei32[2 * i + 1] != 0) any = 1;
    if (any) atomicOr(flag, 1);
}

// --- in-degree (dst side) ---------------------------------------------------
__global__ void k_degree(const void* ei, long long E, const int* flag, float* deg) {
    long long i = blockIdx.x * (long long)blockDim.x + threadIdx.x;
    long long stride = (long long)gridDim.x * blockDim.x;
    int is32 = *flag;
    for (; i < E; i += stride) {
        int d = load_idx(ei, E + i, is32);
        atomicAdd(&deg[d], 1.0f);
    }
}

// --- deg -> 1/sqrt(deg) in place -------------------------------------------
__global__ void k_rsqrt(float* deg, int n) {
    int i = blockIdx.x * blockDim.x + threadIdx.x;
    if (i < n) deg[i] = rsqrtf(deg[i]);
}

// --- self-loop init: out[i,:] = dinv[i]^2 * X[i,:] --------------------------
__global__ void k_selfinit(const float* __restrict__ X, const float* __restrict__ dinv,
                           float* __restrict__ out, long long n4, int D4) {
    long long i = blockIdx.x * (long long)blockDim.x + threadIdx.x;
    long long stride = (long long)gridDim.x * blockDim.x;
    for (; i < n4; i += stride) {
        int row = (int)(i / D4);
        float w = dinv[row]; w *= w;
        float4 v = ((const float4*)X)[i];
        v.x *= w; v.y *= w; v.z *= w; v.w *= w;
        ((float4*)out)[i] = v;
    }
}

// --- edge scatter: out[dst,:] += dinv[s]*dinv[d] * H[src,:] -----------------
// one warp per edge; lane handles D/32 floats as float4s
template<int D>
__global__ __launch_bounds__(256) void k_scatter(const void* __restrict__ ei, long long E,
                                                 const int* __restrict__ flag,
                                                 const float* __restrict__ dinv,
                                                 const float* __restrict__ H,
                                                 float* __restrict__ out) {
    long long warp = (blockIdx.x * (long long)blockDim.x + threadIdx.x) >> 5;
    int lane = threadIdx.x & 31;
    if (warp >= E) return;
    int is32 = *flag;
    int s = load_idx(ei, warp, is32);
    int d = load_idx(ei, E + warp, is32);
    float w = dinv[s] * dinv[d];
    const float4* src = (const float4*)(H + (long long)s * D);
    float* dstp = out + (long long)d * D;
#pragma unroll
    for (int j = 0; j < D / 128; j++) {
        float4 v = src[j * 32 + lane];
        v.x *= w; v.y *= w; v.z *= w; v.w *= w;
        red_add_v4(dstp + j * 128 + lane * 4, v);
    }
}

// --- tiled SGEMM with bias: C[M,N] = A[M,K] @ B[K,N] + bias ------------------
#define BM 64
#define BN 64
#define BK 16
#define ASTR 72   // padded stride (floats) -> conflict-free, 16B aligned

__global__ __launch_bounds__(256) void k_gemm_bias(const float* __restrict__ A,
                                                   const float* __restrict__ Bw,
                                                   const float* __restrict__ bias,
                                                   float* __restrict__ C,
                                                   int M, int N, int K) {
    __shared__ float As[BK * ASTR];
    __shared__ float Bs[BK * BN];
    int tid = threadIdx.x;
    int bm = blockIdx.y * BM;
    int bn = blockIdx.x * BN;

    int arow = tid >> 2;            // 0..63
    int acol = (tid & 3) * 4;       // 0,4,8,12
    int brow = tid >> 4;            // 0..15
    int bcol = (tid & 15) * 4;      // 0..60

    int tx = tid & 15, ty = tid >> 4;
    float acc[4][4] = {};

    for (int k0 = 0; k0 < K; k0 += BK) {
        float4 av = make_float4(0.f, 0.f, 0.f, 0.f);
        int gm = bm + arow;
        if (gm < M) av = *(const float4*)(A + (long long)gm * K + k0 + acol);
        As[(acol + 0) * ASTR + arow] = av.x;
        As[(acol + 1) * ASTR + arow] = av.y;
        As[(acol + 2) * ASTR + arow] = av.z;
        As[(acol + 3) * ASTR + arow] = av.w;

        float4 bv = *(const float4*)(Bw + (long long)(k0 + brow) * N + bn + bcol);
        *(float4*)(Bs + brow * BN + bcol) = bv;
        __syncthreads();

#pragma unroll
        for (int k = 0; k < BK; k++) {
            float4 a4 = *(const float4*)(As + k * ASTR + ty * 4);
            float4 b4 = *(const float4*)(Bs + k * BN + tx * 4);
            float a[4] = {a4.x, a4.y, a4.z, a4.w};
            float b[4] = {b4.x, b4.y, b4.z, b4.w};
#pragma unroll
            for (int i = 0; i < 4; i++)
#pragma unroll
                for (int j = 0; j < 4; j++)
                    acc[i][j] += a[i] * b[j];
        }
        __syncthreads();
    }

    float bb[4];
#pragma unroll
    for (int j = 0; j < 4; j++) bb[j] = bias[bn + tx * 4 + j];
#pragma unroll
    for (int i = 0; i < 4; i++) {
        int gm = bm + ty * 4 + i;
        if (gm < M) {
            float4 o;
            o.x = acc[i][0] + bb[0];
            o.y = acc[i][1] + bb[1];
            o.z = acc[i][2] + bb[2];
            o.w = acc[i][3] + bb[3];
            *(float4*)(C + (long long)gm * N + bn + tx * 4) = o;
        }
    }
}

// --- zero BN accumulators ----------------------------------------------------
__global__ void k_zero_stats(float* s, float* q, int D) {
    int i = blockIdx.x * blockDim.x + threadIdx.x;
    if (i < D) { s[i] = 0.f; q[i] = 0.f; }
}

// --- BN column sums / sumsq --------------------------------------------------
__global__ void k_stats(const float* __restrict__ X, int M, int D,
                        float* __restrict__ sums, float* __restrict__ sumsq) {
    int rpb = (M + gridDim.x - 1) / gridDim.x;
    int r0 = blockIdx.x * rpb;
    int r1 = min(M, r0 + rpb);
    for (int c = threadIdx.x; c < D; c += blockDim.x) {
        float s = 0.f, q = 0.f;
        for (int r = r0; r < r1; r++) {
            float v = X[(long long)r * D + c];
            s += v; q += v * v;
        }
        atomicAdd(&sums[c], s);
        atomicAdd(&sumsq[c], q);
    }
}

// --- BN apply + ReLU (in place) ----------------------------------------------
__global__ void k_bnrelu(float* __restrict__ X, long long n4, int D4,
                         const float* __restrict__ sums, const float* __restrict__ sumsq,
                         const float* __restrict__ gamma, const float* __restrict__ beta,
                         float invM) {
    long long i = blockIdx.x * (long long)blockDim.x + threadIdx.x;
    long long stride = (long long)gridDim.x * blockDim.x;
    for (; i < n4; i += stride) {
        int c = (int)(i % D4) * 4;
        float4 v = ((float4*)X)[i];
        float o[4] = {v.x, v.y, v.z, v.w};
#pragma unroll
        for (int j = 0; j < 4; j++) {
            float mu = sums[c + j] * invM;
            float var = sumsq[c + j] * invM - mu * mu;
            float sc = gamma[c + j] * rsqrtf(var + EPS);
            o[j] = fmaxf((o[j] - mu) * sc + beta[c + j], 0.f);
        }
        v.x = o[0]; v.y = o[1]; v.z = o[2]; v.w = o[3];
        ((float4*)X)[i] = v;
    }
}

// ---------------------------------------------------------------------------

extern "C" void kernel_launch(void* const* d_in, const int* in_sizes, int n_in,
                              void* d_out, int out_size) {
    const float* x      = (const float*)d_in[0];
    const void*  ei     = d_in[1];
    const float* W1     = (const float*)d_in[2];
    const float* b1     = (const float*)d_in[3];
    const float* gamma1 = (const float*)d_in[4];
    const float* beta1  = (const float*)d_in[5];
    const float* W2     = (const float*)d_in[6];
    const float* b2     = (const float*)d_in[7];
    const float* gamma2 = (const float*)d_in[8];
    const float* beta2  = (const float*)d_in[9];
    const float* Wl     = (const float*)d_in[10];
    const float* bl     = (const float*)d_in[11];

    const int H1   = in_sizes[3];               // 256
    const int H2   = in_sizes[7];               // 512
    const int DOUT = in_sizes[11];              // 128
    const int DIN  = in_sizes[2] / H1;          // 128
    const int N    = in_sizes[0] / DIN;         // 50000
    const long long E = in_sizes[1] / 2;        // 500000
    const float invM = 1.0f / (float)N;

    float *deg, *agg1, *h1, *agg2, *h2, *sums, *sumsq;
    int* flag;
    cudaGetSymbolAddress((void**)&deg,   g_deg);
    cudaGetSymbolAddress((void**)&agg1,  g_agg1);
    cudaGetSymbolAddress((void**)&h1,    g_h1);
    cudaGetSymbolAddress((void**)&agg2,  g_agg2);
    cudaGetSymbolAddress((void**)&h2,    g_h2);
    cudaGetSymbolAddress((void**)&sums,  g_sums);
    cudaGetSymbolAddress((void**)&sumsq, g_sumsq);
    cudaGetSymbolAddress((void**)&flag,  g_flag32);

    float* out = (float*)d_out;

    // 1. norm prep
    k_init<<<(N + 255) / 256, 256>>>(deg, N, flag);
    k_detect<<<1024, 256>>>((const int*)ei, E, flag);
    k_degree<<<1024, 256>>>(ei, E, flag, deg);
    k_rsqrt<<<(N + 255) / 256, 256>>>(deg, N);

    // 2. layer 1: agg1 = A x ; h1 = BNReLU(agg1 @ W1 + b1)
    {
        long long n4 = (long long)N * DIN / 4;
        k_selfinit<<<(int)((n4 + 255) / 256), 256>>>(x, deg, agg1, n4, DIN / 4);
        long long blocks = (E * 32 + 255) / 256;
        k_scatter<128><<<(int)blocks, 256>>>(ei, E, flag, deg, x, agg1);
        dim3 grid(H1 / BN, (N + BM - 1) / BM);
        k_gemm_bias<<<grid, 256>>>(agg1, W1, b1, h1, N, H1, DIN);
        k_zero_stats<<<(H1 + 255) / 256, 256>>>(sums, sumsq, H1);
        k_stats<<<512, 256>>>(h1, N, H1, sums, sumsq);
        long long h4 = (long long)N * H1 / 4;
        k_bnrelu<<<(int)((h4 + 255) / 256), 256>>>(h1, h4, H1 / 4, sums, sumsq, gamma1, beta1, invM);
    }

    // 3. layer 2: agg2 = A h1 ; h2 = BNReLU(agg2 @ W2 + b2)
    {
        long long n4 = (long long)N * H1 / 4;
        k_selfinit<<<(int)((n4 + 255) / 256), 256>>>(h1, deg, agg2, n4, H1 / 4);
        long long blocks = (E * 32 + 255) / 256;
        k_scatter<256><<<(int)blocks, 256>>>(ei, E, flag, deg, h1, agg2);
        dim3 grid(H2 / BN, (N + BM - 1) / BM);
        k_gemm_bias<<<grid, 256>>>(agg2, W2, b2, h2, N, H2, H1);
        k_zero_stats<<<(H2 + 255) / 256, 256>>>(sums, sumsq, H2);
        k_stats<<<512, 256>>>(h2, N, H2, sums, sumsq);
        long long h4 = (long long)N * H2 / 4;
        k_bnrelu<<<(int)((h4 + 255) / 256), 256>>>(h2, h4, H2 / 4, sums, sumsq, gamma2, beta2, invM);
    }

    // 4. final projection: out = h2 @ Wl + bl
    {
        dim3 grid(DOUT / BN, (N + BM - 1) / BM);
        k_gemm_bias<<<grid, 256>>>(h2, Wl, bl, out, N, DOUT, H2);
    }
}

// round 2
// speedup vs baseline: 1.7731x; 1.7731x over previous
#include <cuda_runtime.h>
#include <cuda_bf16.h>
#include <cstdint>

// ---------------------------------------------------------------------------
// GCN encoder: N=50000, E=500000, 128 -> 256 -> 512 -> 128
// agg-first formulation: layer_k = BNReLU( (A x_in) @ W + b )
// GEMMs on tensor cores (mma.sync tf32), scatter via red.global.add.v4
// ---------------------------------------------------------------------------

#define MAXN 50048
#define EPS 1e-5f

__device__ float g_deg[MAXN];                 // degree -> dinv (in place)
__device__ float g_agg1[(size_t)MAXN * 128];
__device__ float g_h1[(size_t)MAXN * 256];
__device__ float g_agg2[(size_t)MAXN * 256];
__device__ float g_h2[(size_t)MAXN * 512];
__device__ float g_sums[512];
__device__ float g_sumsq[512];
__device__ int   g_flag32;                    // 1 => edge_index is int32

// ---------------------------------------------------------------------------

__device__ __forceinline__ void red_add_v4(float* addr, float4 v) {
    asm volatile("red.global.add.v4.f32 [%0], {%1,%2,%3,%4};"
                 :: "l"(addr), "f"(v.x), "f"(v.y), "f"(v.z), "f"(v.w)
                 : "memory");
}

__device__ __forceinline__ int load_idx(const void* ei, long long pos, int is32) {
    if (is32) return ((const int*)ei)[pos];
    return (int)(((const long long*)ei)[pos]);
}

__device__ __forceinline__ uint32_t f2tf32(float f) {
    uint32_t u;
    asm("cvt.rna.tf32.f32 %0, %1;" : "=r"(u) : "f"(f));
    return u;
}

// --- init: deg = 1 (self loop), flag = 0 ----------------------------------
__global__ void k_init(float* deg, int n, int* flag) {
    int i = blockIdx.x * blockDim.x + threadIdx.x;
    if (i < n) deg[i] = 1.0f;
    if (i == 0) *flag = 0;
}

// --- detect int32 vs int64: odd 32-bit words all zero <=> int64 -----------
__global__ void k_detect(const int* ei32, long long E, int* flag) {
    long long i = blockIdx.x * (long long)blockDim.x + threadIdx.x;
    long long stride = (long long)gridDim.x * blockDim.x;
    int any = 0;
    for (; i < E; i += stride)
        if (ei32[2 * i + 1] != 0) any = 1;
    if (any) atomicOr(flag, 1);
}

// --- in-degree (dst side) ---------------------------------------------------
__global__ void k_degree(const void* ei, long long E, const int* flag, float* deg) {
    long long i = blockIdx.x * (long long)blockDim.x + threadIdx.x;
    long long stride = (long long)gridDim.x * blockDim.x;
    int is32 = *flag;
    for (; i < E; i += stride) {
        int d = load_idx(ei, E + i, is32);
        atomicAdd(&deg[d], 1.0f);
    }
}

// --- deg -> 1/sqrt(deg) in place -------------------------------------------
__global__ void k_rsqrt(float* deg, int n) {
    int i = blockIdx.x * blockDim.x + threadIdx.x;
    if (i < n) deg[i] = rsqrtf(deg[i]);
}

// --- self-loop init: out[i,:] = dinv[i]^2 * X[i,:] --------------------------
__global__ void k_selfinit(const float* __restrict__ X, const float* __restrict__ dinv,
                           float* __restrict__ out, long long n4, int D4) {
    long long i = blockIdx.x * (long long)blockDim.x + threadIdx.x;
    long long stride = (long long)gridDim.x * blockDim.x;
    for (; i < n4; i += stride) {
        int row = (int)(i / D4);
        float w = dinv[row]; w *= w;
        float4 v = ((const float4*)X)[i];
        v.x *= w; v.y *= w; v.z *= w; v.w *= w;
        ((float4*)out)[i] = v;
    }
}

// --- edge scatter: out[dst,:] += dinv[s]*dinv[d] * H[src,:] -----------------
template<int D>
__global__ __launch_bounds__(256) void k_scatter(const void* __restrict__ ei, long long E,
                                                 const int* __restrict__ flag,
                                                 const float* __restrict__ dinv,
                                                 const float* __restrict__ H,
                                                 float* __restrict__ out) {
    long long warp = (blockIdx.x * (long long)blockDim.x + threadIdx.x) >> 5;
    int lane = threadIdx.x & 31;
    if (warp >= E) return;
    int is32 = *flag;
    int s = load_idx(ei, warp, is32);
    int d = load_idx(ei, E + warp, is32);
    float w = dinv[s] * dinv[d];
    const float4* src = (const float4*)(H + (long long)s * D);
    float* dstp = out + (long long)d * D;
#pragma unroll
    for (int j = 0; j < D / 128; j++) {
        float4 v = src[j * 32 + lane];
        v.x *= w; v.y *= w; v.z *= w; v.w *= w;
        red_add_v4(dstp + j * 128 + lane * 4, v);
    }
}

// ---------------------------------------------------------------------------
// Tensor-core GEMM: C[M,N] = A[M,K] @ B[K,N] + bias, tf32 mma.sync
// Block tile 128x128, 8 warps (warp tile 32x64), BK=32.
// ---------------------------------------------------------------------------
#define GBM 128
#define GBN 128
#define GBK 32
#define ASTRIDE 36    // 32 + 4 pad
#define BSTRIDE 132   // 128 + 4 pad

__global__ __launch_bounds__(256) void k_gemm_tc(const float* __restrict__ A,
                                                 const float* __restrict__ Bw,
                                                 const float* __restrict__ bias,
                                                 float* __restrict__ C,
                                                 int M, int N, int K) {
    __shared__ float As[GBM * ASTRIDE];   // [m][k]
    __shared__ float Bs[GBK * BSTRIDE];   // [k][n]

    const int tid  = threadIdx.x;
    const int lane = tid & 31;
    const int warpId = tid >> 5;
    const int warpM = warpId & 3;     // 0..3  -> 32-row slice
    const int warpN = warpId >> 2;    // 0..1  -> 64-col slice
    const int g = lane >> 2;          // group id 0..7
    const int t = lane & 3;           // thread-in-group 0..3

    const int bm = blockIdx.y * GBM;
    const int bn = blockIdx.x * GBN;

    float4 acc[2][8];
#pragma unroll
    for (int i = 0; i < 2; i++)
#pragma unroll
        for (int j = 0; j < 8; j++)
            acc[i][j] = make_float4(0.f, 0.f, 0.f, 0.f);

    // A tile load map: 4 iters, row = i*32 + tid/8, col4 = (tid%8)*4
    const int a_row = tid >> 3;
    const int a_col = (tid & 7) * 4;
    // B tile load map: 4 iters, k = i*8 + tid/32, n4 = (tid%32)*4
    const int b_k  = tid >> 5;
    const int b_n4 = (tid & 31) * 4;

    for (int k0 = 0; k0 < K; k0 += GBK) {
        // load A 128x32
#pragma unroll
        for (int i = 0; i < 4; i++) {
            int row = i * 32 + a_row;
            int gm = bm + row;
            float4 v = make_float4(0.f, 0.f, 0.f, 0.f);
            if (gm < M) v = *(const float4*)(A + (long long)gm * K + k0 + a_col);
            float* p = As + row * ASTRIDE + a_col;
            p[0] = __uint_as_float(f2tf32(v.x));
            p[1] = __uint_as_float(f2tf32(v.y));
            p[2] = __uint_as_float(f2tf32(v.z));
            p[3] = __uint_as_float(f2tf32(v.w));
        }
        // load B 32x128 (N assumed multiple of 128)
#pragma unroll
        for (int i = 0; i < 4; i++) {
            int kk = i * 8 + b_k;
            float4 v = *(const float4*)(Bw + (long long)(k0 + kk) * N + bn + b_n4);
            float* p = Bs + kk * BSTRIDE + b_n4;
            p[0] = __uint_as_float(f2tf32(v.x));
            p[1] = __uint_as_float(f2tf32(v.y));
            p[2] = __uint_as_float(f2tf32(v.z));
            p[3] = __uint_as_float(f2tf32(v.w));
        }
        __syncthreads();

#pragma unroll
        for (int kk = 0; kk < GBK; kk += 8) {
            uint32_t afrag[2][4];
            uint32_t bfrag[8][2];
#pragma unroll
            for (int im = 0; im < 2; im++) {
                const float* base = As + (warpM * 32 + im * 16 + g) * ASTRIDE + kk + t;
                afrag[im][0] = __float_as_uint(base[0]);
                afrag[im][1] = __float_as_uint(base[8 * ASTRIDE]);
                afrag[im][2] = __float_as_uint(base[4]);
                afrag[im][3] = __float_as_uint(base[8 * ASTRIDE + 4]);
            }
#pragma unroll
            for (int jn = 0; jn < 8; jn++) {
                int n = warpN * 64 + jn * 8 + g;
                bfrag[jn][0] = __float_as_uint(Bs[(kk + t) * BSTRIDE + n]);
                bfrag[jn][1] = __float_as_uint(Bs[(kk + t + 4) * BSTRIDE + n]);
            }
#pragma unroll
            for (int im = 0; im < 2; im++)
#pragma unroll
                for (int jn = 0; jn < 8; jn++) {
                    float4& c = acc[im][jn];
                    asm volatile(
                        "mma.sync.aligned.m16n8k8.row.col.f32.tf32.tf32.f32 "
                        "{%0,%1,%2,%3}, {%4,%5,%6,%7}, {%8,%9}, {%0,%1,%2,%3};"
                        : "+f"(c.x), "+f"(c.y), "+f"(c.z), "+f"(c.w)
                        : "r"(afrag[im][0]), "r"(afrag[im][1]),
                          "r"(afrag[im][2]), "r"(afrag[im][3]),
                          "r"(bfrag[jn][0]), "r"(bfrag[jn][1]));
                }
        }
        __syncthreads();
    }

    // epilogue: C fragment layout c0:(g, 2t) c1:(g, 2t+1) c2:(g+8, 2t) c3:(g+8, 2t+1)
#pragma unroll
    for (int jn = 0; jn < 8; jn++) {
        int col = bn + warpN * 64 + jn * 8 + 2 * t;
        float bx = bias[col], by = bias[col + 1];
#pragma unroll
        for (int im = 0; im < 2; im++) {
            int row0 = bm + warpM * 32 + im * 16 + g;
            float4 c = acc[im][jn];
            if (row0 < M) {
                float2 o = make_float2(c.x + bx, c.y + by);
                *(float2*)(C + (long long)row0 * N + col) = o;
            }
            if (row0 + 8 < M) {
                float2 o = make_float2(c.z + bx, c.w + by);
                *(float2*)(C + (long long)(row0 + 8) * N + col) = o;
            }
        }
    }
}

// --- zero BN accumulators ----------------------------------------------------
__global__ void k_zero_stats(float* s, float* q, int D) {
    int i = blockIdx.x * blockDim.x + threadIdx.x;
    if (i < D) { s[i] = 0.f; q[i] = 0.f; }
}

// --- BN column sums / sumsq --------------------------------------------------
__global__ void k_stats(const float* __restrict__ X, int M, int D,
                        float* __restrict__ sums, float* __restrict__ sumsq) {
    int rpb = (M + gridDim.x - 1) / gridDim.x;
    int r0 = blockIdx.x * rpb;
    int r1 = min(M, r0 + rpb);
    for (int c = threadIdx.x; c < D; c += blockDim.x) {
        float s = 0.f, q = 0.f;
        for (int r = r0; r < r1; r++) {
            float v = X[(long long)r * D + c];
            s += v; q += v * v;
        }
        atomicAdd(&sums[c], s);
        atomicAdd(&sumsq[c], q);
    }
}

// --- BN apply + ReLU (in place) ----------------------------------------------
__global__ void k_bnrelu(float* __restrict__ X, long long n4, int D4,
                         const float* __restrict__ sums, const float* __restrict__ sumsq,
                         const float* __restrict__ gamma, const float* __restrict__ beta,
                         float invM) {
    long long i = blockIdx.x * (long long)blockDim.x + threadIdx.x;
    long long stride = (long long)gridDim.x * blockDim.x;
    for (; i < n4; i += stride) {
        int c = (int)(i % D4) * 4;
        float4 v = ((float4*)X)[i];
        float o[4] = {v.x, v.y, v.z, v.w};
#pragma unroll
        for (int j = 0; j < 4; j++) {
            float mu = sums[c + j] * invM;
            float var = sumsq[c + j] * invM - mu * mu;
            float sc = gamma[c + j] * rsqrtf(var + EPS);
            o[j] = fmaxf((o[j] - mu) * sc + beta[c + j], 0.f);
        }
        v.x = o[0]; v.y = o[1]; v.z = o[2]; v.w = o[3];
        ((float4*)X)[i] = v;
    }
}

// ---------------------------------------------------------------------------

extern "C" void kernel_launch(void* const* d_in, const int* in_sizes, int n_in,
                              void* d_out, int out_size) {
    const float* x      = (const float*)d_in[0];
    const void*  ei     = d_in[1];
    const float* W1     = (const float*)d_in[2];
    const float* b1     = (const float*)d_in[3];
    const float* gamma1 = (const float*)d_in[4];
    const float* beta1  = (const float*)d_in[5];
    const float* W2     = (const float*)d_in[6];
    const float* b2     = (const float*)d_in[7];
    const float* gamma2 = (const float*)d_in[8];
    const float* beta2  = (const float*)d_in[9];
    const float* Wl     = (const float*)d_in[10];
    const float* bl     = (const float*)d_in[11];

    const int H1   = in_sizes[3];               // 256
    const int H2   = in_sizes[7];               // 512
    const int DOUT = in_sizes[11];              // 128
    const int DIN  = in_sizes[2] / H1;          // 128
    const int N    = in_sizes[0] / DIN;         // 50000
    const long long E = in_sizes[1] / 2;        // 500000
    const float invM = 1.0f / (float)N;

    float *deg, *agg1, *h1, *agg2, *h2, *sums, *sumsq;
    int* flag;
    cudaGetSymbolAddress((void**)&deg,   g_deg);
    cudaGetSymbolAddress((void**)&agg1,  g_agg1);
    cudaGetSymbolAddress((void**)&h1,    g_h1);
    cudaGetSymbolAddress((void**)&agg2,  g_agg2);
    cudaGetSymbolAddress((void**)&h2,    g_h2);
    cudaGetSymbolAddress((void**)&sums,  g_sums);
    cudaGetSymbolAddress((void**)&sumsq, g_sumsq);
    cudaGetSymbolAddress((void**)&flag,  g_flag32);

    float* out = (float*)d_out;

    // 1. norm prep
    k_init<<<(N + 255) / 256, 256>>>(deg, N, flag);
    k_detect<<<1024, 256>>>((const int*)ei, E, flag);
    k_degree<<<1024, 256>>>(ei, E, flag, deg);
    k_rsqrt<<<(N + 255) / 256, 256>>>(deg, N);

    // 2. layer 1: agg1 = A x ; h1 = BNReLU(agg1 @ W1 + b1)
    {
        long long n4 = (long long)N * DIN / 4;
        k_selfinit<<<(int)((n4 + 255) / 256), 256>>>(x, deg, agg1, n4, DIN / 4);
        long long blocks = (E * 32 + 255) / 256;
        k_scatter<128><<<(int)blocks, 256>>>(ei, E, flag, deg, x, agg1);
        dim3 grid(H1 / GBN, (N + GBM - 1) / GBM);
        k_gemm_tc<<<grid, 256>>>(agg1, W1, b1, h1, N, H1, DIN);
        k_zero_stats<<<(H1 + 255) / 256, 256>>>(sums, sumsq, H1);
        k_stats<<<512, 256>>>(h1, N, H1, sums, sumsq);
        long long h4 = (long long)N * H1 / 4;
        k_bnrelu<<<(int)((h4 + 255) / 256), 256>>>(h1, h4, H1 / 4, sums, sumsq, gamma1, beta1, invM);
    }

    // 3. layer 2: agg2 = A h1 ; h2 = BNReLU(agg2 @ W2 + b2)
    {
        long long n4 = (long long)N * H1 / 4;
        k_selfinit<<<(int)((n4 + 255) / 256), 256>>>(h1, deg, agg2, n4, H1 / 4);
        long long blocks = (E * 32 + 255) / 256;
        k_scatter<256><<<(int)blocks, 256>>>(ei, E, flag, deg, h1, agg2);
        dim3 grid(H2 / GBN, (N + GBM - 1) / GBM);
        k_gemm_tc<<<grid, 256>>>(agg2, W2, b2, h2, N, H2, H1);
        k_zero_stats<<<(H2 + 255) / 256, 256>>>(sums, sumsq, H2);
        k_stats<<<512, 256>>>(h2, N, H2, sums, sumsq);
        long long h4 = (long long)N * H2 / 4;
        k_bnrelu<<<(int)((h4 + 255) / 256), 256>>>(h2, h4, H2 / 4, sums, sumsq, gamma2, beta2, invM);
    }

    // 4. final projection: out = h2 @ Wl + bl
    {
        dim3 grid(DOUT / GBN, (N + GBM - 1) / GBM);
        k_gemm_tc<<<grid, 256>>>(h2, Wl, bl, out, N, DOUT, H2);
    }
}

// round 3
// speedup vs baseline: 2.2146x; 1.2490x over previous
#include <cuda_runtime.h>
#include <cuda_bf16.h>
#include <cstdint>

// ---------------------------------------------------------------------------
// GCN encoder: N=50000, E=500000, 128 -> 256 -> 512 -> 128
// CSR gather aggregation + tf32 tensor-core GEMM w/ fused BN stats
// ---------------------------------------------------------------------------

#define MAXN 50048
#define MAXE 524288
#define EPS 1e-5f

__device__ float  g_dinv[MAXN];
__device__ int    g_cnt[MAXN];
__device__ int    g_rowptr[MAXN + 1];
__device__ int    g_cursor[MAXN];
__device__ int2   g_adj[MAXE];                 // (src, bits(w))
__device__ float  g_agg1[(size_t)MAXN * 128];
__device__ float  g_h1[(size_t)MAXN * 256];
__device__ float  g_agg2[(size_t)MAXN * 256];
__device__ float  g_h2[(size_t)MAXN * 512];
__device__ float2 g_stats1[256];               // (sum, sumsq) per col
__device__ float2 g_stats2[512];
__device__ float2 g_ss1[256];                  // (scale, shift) per col
__device__ float2 g_ss2[512];
__device__ int    g_flag32;                    // 1 => edge_index is int32

// ---------------------------------------------------------------------------

__device__ __forceinline__ void red_add_v2(float2* addr, float a, float b) {
    asm volatile("red.global.add.v2.f32 [%0], {%1,%2};"
                 :: "l"(addr), "f"(a), "f"(b) : "memory");
}

__device__ __forceinline__ int load_idx(const void* ei, long long pos, int is32) {
    if (is32) return ((const int*)ei)[pos];
    return (int)(((const long long*)ei)[pos]);
}

__device__ __forceinline__ uint32_t f2tf32(float f) {
    uint32_t u;
    asm("cvt.rna.tf32.f32 %0, %1;" : "=r"(u) : "f"(f));
    return u;
}

// --- init: cnt = 0, flag = 0, stats = 0 -------------------------------------
__global__ void k_init(int* cnt, int n, int* flag, float2* st1, float2* st2,
                       int d1, int d2) {
    int i = blockIdx.x * blockDim.x + threadIdx.x;
    if (i < n) cnt[i] = 0;
    if (i == 0) *flag = 0;
    if (i < d1) st1[i] = make_float2(0.f, 0.f);
    if (i < d2) st2[i] = make_float2(0.f, 0.f);
}

// --- detect int32 vs int64: odd 32-bit words all zero <=> int64 -------------
__global__ void k_detect(const int* ei32, long long E, int* flag) {
    long long i = blockIdx.x * (long long)blockDim.x + threadIdx.x;
    long long stride = (long long)gridDim.x * blockDim.x;
    int any = 0;
    for (; i < E; i += stride)
        if (ei32[2 * i + 1] != 0) any = 1;
    if (any) atomicOr(flag, 1);
}

// --- in-degree counts (dst side) ---------------------------------------------
__global__ void k_count(const void* ei, long long E, const int* flag, int* cnt) {
    long long i = blockIdx.x * (long long)blockDim.x + threadIdx.x;
    long long stride = (long long)gridDim.x * blockDim.x;
    int is32 = *flag;
    for (; i < E; i += stride) {
        int d = load_idx(ei, E + i, is32);
        atomicAdd(&cnt[d], 1);
    }
}

// --- single-block scan: rowptr/cursor = exclusive scan(cnt); dinv = rsqrt ----
__global__ __launch_bounds__(1024) void k_scan(const int* __restrict__ cnt,
                                               int* __restrict__ rowptr,
                                               int* __restrict__ cursor,
                                               float* __restrict__ dinv, int n) {
    __shared__ int warpsum[32];
    __shared__ int s_carry;
    if (threadIdx.x == 0) s_carry = 0;
    __syncthreads();
    int lane = threadIdx.x & 31, wid = threadIdx.x >> 5;
    for (int base = 0; base < n; base += 1024) {
        int i = base + (int)threadIdx.x;
        int v = (i < n) ? cnt[i] : 0;
        int x = v;
#pragma unroll
        for (int off = 1; off < 32; off <<= 1) {
            int y = __shfl_up_sync(0xffffffffu, x, off);
            if (lane >= off) x += y;
        }
        if (lane == 31) warpsum[wid] = x;
        __syncthreads();
        if (wid == 0) {
            int w = warpsum[lane];
#pragma unroll
            for (int off = 1; off < 32; off <<= 1) {
                int y = __shfl_up_sync(0xffffffffu, w, off);
                if (lane >= off) w += y;
            }
            warpsum[lane] = w;
        }
        __syncthreads();
        int incl = x + (wid > 0 ? warpsum[wid - 1] : 0) + s_carry;
        int excl = incl - v;
        if (i < n) {
            rowptr[i] = excl;
            cursor[i] = excl;
            dinv[i] = rsqrtf((float)v + 1.0f);
        }
        __syncthreads();
        if (threadIdx.x == 1023) s_carry = incl;
        __syncthreads();
    }
    if (threadIdx.x == 0) rowptr[n] = s_carry;
}

// --- bucket-fill adjacency ----------------------------------------------------
__global__ void k_fill(const void* __restrict__ ei, long long E, const int* flag,
                       const float* __restrict__ dinv, int* __restrict__ cursor,
                       int2* __restrict__ adj) {
    long long i = blockIdx.x * (long long)blockDim.x + threadIdx.x;
    long long stride = (long long)gridDim.x * blockDim.x;
    int is32 = *flag;
    for (; i < E; i += stride) {
        int s = load_idx(ei, i, is32);
        int d = load_idx(ei, E + i, is32);
        float w = dinv[s] * dinv[d];
        int pos = atomicAdd(&cursor[d], 1);
        adj[pos] = make_int2(s, __float_as_int(w));
    }
}

// --- CSR aggregation: out[i,:] = dinv[i]^2 X[i,:] + sum_j w_j X[src_j,:] -----
// one warp per node, lane owns D/32 floats
template<int D>
__global__ __launch_bounds__(256) void k_agg(const int2* __restrict__ adj,
                                             const int* __restrict__ rowptr,
                                             const float* __restrict__ dinv,
                                             const float* __restrict__ X,
                                             float* __restrict__ out, int N) {
    int node = (int)((blockIdx.x * (long long)blockDim.x + threadIdx.x) >> 5);
    int lane = threadIdx.x & 31;
    if (node >= N) return;
    constexpr int V = D / 128;
    float4 acc[V];
    float w0 = dinv[node]; w0 *= w0;
    const float4* xs = (const float4*)(X + (size_t)node * D);
#pragma unroll
    for (int v = 0; v < V; v++) {
        float4 a = xs[v * 32 + lane];
        acc[v] = make_float4(a.x * w0, a.y * w0, a.z * w0, a.w * w0);
    }
    int j = rowptr[node], end = rowptr[node + 1];
    int2 e = (j < end) ? adj[j] : make_int2(0, 0);
    for (; j < end; j++) {
        int2 cur = e;
        if (j + 1 < end) e = adj[j + 1];             // prefetch next
        float w = __int_as_float(cur.y);
        const float4* s = (const float4*)(X + (size_t)cur.x * D);
#pragma unroll
        for (int v = 0; v < V; v++) {
            float4 a = s[v * 32 + lane];
            acc[v].x += w * a.x; acc[v].y += w * a.y;
            acc[v].z += w * a.z; acc[v].w += w * a.w;
        }
    }
    float4* o = (float4*)(out + (size_t)node * D);
#pragma unroll
    for (int v = 0; v < V; v++) o[v * 32 + lane] = acc[v];
}

// ---------------------------------------------------------------------------
// Tensor-core GEMM: C[M,N] = A[M,K] @ B[K,N] + bias, tf32 mma.sync.
// Optionally accumulates per-column (sum, sumsq) BN stats via red.v2.
// Block tile 128x128, 8 warps (warp tile 32x64), BK=32.
// ---------------------------------------------------------------------------
#define GBM 128
#define GBN 128
#define GBK 32
#define ASTRIDE 36
#define BSTRIDE 132

__global__ __launch_bounds__(256) void k_gemm_tc(const float* __restrict__ A,
                                                 const float* __restrict__ Bw,
                                                 const float* __restrict__ bias,
                                                 float* __restrict__ C,
                                                 float2* __restrict__ stats,
                                                 int M, int N, int K) {
    __shared__ float As[GBM * ASTRIDE];   // [m][k]
    __shared__ float Bs[GBK * BSTRIDE];   // [k][n]

    const int tid  = threadIdx.x;
    const int lane = tid & 31;
    const int warpId = tid >> 5;
    const int warpM = warpId & 3;
    const int warpN = warpId >> 2;
    const int g = lane >> 2;
    const int t = lane & 3;

    const int bm = blockIdx.y * GBM;
    const int bn = blockIdx.x * GBN;

    float4 acc[2][8];
#pragma unroll
    for (int i = 0; i < 2; i++)
#pragma unroll
        for (int j = 0; j < 8; j++)
            acc[i][j] = make_float4(0.f, 0.f, 0.f, 0.f);

    const int a_row = tid >> 3;
    const int a_col = (tid & 7) * 4;
    const int b_k  = tid >> 5;
    const int b_n4 = (tid & 31) * 4;

    for (int k0 = 0; k0 < K; k0 += GBK) {
#pragma unroll
        for (int i = 0; i < 4; i++) {
            int row = i * 32 + a_row;
            int gm = bm + row;
            float4 v = make_float4(0.f, 0.f, 0.f, 0.f);
            if (gm < M) v = *(const float4*)(A + (long long)gm * K + k0 + a_col);
            float* p = As + row * ASTRIDE + a_col;
            p[0] = __uint_as_float(f2tf32(v.x));
            p[1] = __uint_as_float(f2tf32(v.y));
            p[2] = __uint_as_float(f2tf32(v.z));
            p[3] = __uint_as_float(f2tf32(v.w));
        }
#pragma unroll
        for (int i = 0; i < 4; i++) {
            int kk = i * 8 + b_k;
            float4 v = *(const float4*)(Bw + (long long)(k0 + kk) * N + bn + b_n4);
            float* p = Bs + kk * BSTRIDE + b_n4;
            p[0] = __uint_as_float(f2tf32(v.x));
            p[1] = __uint_as_float(f2tf32(v.y));
            p[2] = __uint_as_float(f2tf32(v.z));
            p[3] = __uint_as_float(f2tf32(v.w));
        }
        __syncthreads();

#pragma unroll
        for (int kk = 0; kk < GBK; kk += 8) {
            uint32_t afrag[2][4];
            uint32_t bfrag[8][2];
#pragma unroll
            for (int im = 0; im < 2; im++) {
                const float* base = As + (warpM * 32 + im * 16 + g) * ASTRIDE + kk + t;
                afrag[im][0] = __float_as_uint(base[0]);
                afrag[im][1] = __float_as_uint(base[8 * ASTRIDE]);
                afrag[im][2] = __float_as_uint(base[4]);
                afrag[im][3] = __float_as_uint(base[8 * ASTRIDE + 4]);
            }
#pragma unroll
            for (int jn = 0; jn < 8; jn++) {
                int n = warpN * 64 + jn * 8 + g;
                bfrag[jn][0] = __float_as_uint(Bs[(kk + t) * BSTRIDE + n]);
                bfrag[jn][1] = __float_as_uint(Bs[(kk + t + 4) * BSTRIDE + n]);
            }
#pragma unroll
            for (int im = 0; im < 2; im++)
#pragma unroll
                for (int jn = 0; jn < 8; jn++) {
                    float4& c = acc[im][jn];
                    asm volatile(
                        "mma.sync.aligned.m16n8k8.row.col.f32.tf32.tf32.f32 "
                        "{%0,%1,%2,%3}, {%4,%5,%6,%7}, {%8,%9}, {%0,%1,%2,%3};"
                        : "+f"(c.x), "+f"(c.y), "+f"(c.z), "+f"(c.w)
                        : "r"(afrag[im][0]), "r"(afrag[im][1]),
                          "r"(afrag[im][2]), "r"(afrag[im][3]),
                          "r"(bfrag[jn][0]), "r"(bfrag[jn][1]));
                }
        }
        __syncthreads();
    }

    // epilogue: bias add, store, fused BN stat accumulation
#pragma unroll
    for (int jn = 0; jn < 8; jn++) {
        int col = bn + warpN * 64 + jn * 8 + 2 * t;
        float bx = bias[col], by = bias[col + 1];
        float s0 = 0.f, q0 = 0.f, s1 = 0.f, q1 = 0.f;
#pragma unroll
        for (int im = 0; im < 2; im++) {
            int row0 = bm + warpM * 32 + im * 16 + g;
            float4 c = acc[im][jn];
            if (row0 < M) {
                float ox = c.x + bx, oy = c.y + by;
                *(float2*)(C + (long long)row0 * N + col) = make_float2(ox, oy);
                s0 += ox; q0 += ox * ox; s1 += oy; q1 += oy * oy;
            }
            if (row0 + 8 < M) {
                float oz = c.z + bx, ow = c.w + by;
                *(float2*)(C + (long long)(row0 + 8) * N + col) = make_float2(oz, ow);
                s0 += oz; q0 += oz * oz; s1 += ow; q1 += ow * ow;
            }
        }
        if (stats != nullptr) {
#pragma unroll
            for (int m = 4; m < 32; m <<= 1) {
                s0 += __shfl_xor_sync(0xffffffffu, s0, m);
                q0 += __shfl_xor_sync(0xffffffffu, q0, m);
                s1 += __shfl_xor_sync(0xffffffffu, s1, m);
                q1 += __shfl_xor_sync(0xffffffffu, q1, m);
            }
            if (g == 0) {
                red_add_v2(&stats[col], s0, q0);
                red_add_v2(&stats[col + 1], s1, q1);
            }
        }
    }
}

// --- stats -> per-col (scale, shift) -----------------------------------------
__global__ void k_bnprep(const float2* __restrict__ stats,
                         const float* __restrict__ gamma,
                         const float* __restrict__ beta,
                         float2* __restrict__ ss, int D, float invM) {
    int c = blockIdx.x * blockDim.x + threadIdx.x;
    if (c < D) {
        float mu = stats[c].x * invM;
        float var = stats[c].y * invM - mu * mu;
        float sc = gamma[c] * rsqrtf(var + EPS);
        ss[c] = make_float2(sc, beta[c] - mu * sc);
    }
}

// --- BN apply + ReLU (in place) ------------------------------------------------
__global__ void k_bnrelu(float* __restrict__ X, long long n4, int D4,
                         const float2* __restrict__ ss) {
    long long i = blockIdx.x * (long long)blockDim.x + threadIdx.x;
    long long stride = (long long)gridDim.x * blockDim.x;
    for (; i < n4; i += stride) {
        int c = (int)(i % D4) * 4;
        float4 v = ((float4*)X)[i];
        float2 s0 = ss[c], s1 = ss[c + 1], s2 = ss[c + 2], s3 = ss[c + 3];
        v.x = fmaxf(fmaf(v.x, s0.x, s0.y), 0.f);
        v.y = fmaxf(fmaf(v.y, s1.x, s1.y), 0.f);
        v.z = fmaxf(fmaf(v.z, s2.x, s2.y), 0.f);
        v.w = fmaxf(fmaf(v.w, s3.x, s3.y), 0.f);
        ((float4*)X)[i] = v;
    }
}

// ---------------------------------------------------------------------------

extern "C" void kernel_launch(void* const* d_in, const int* in_sizes, int n_in,
                              void* d_out, int out_size) {
    const float* x      = (const float*)d_in[0];
    const void*  ei     = d_in[1];
    const float* W1     = (const float*)d_in[2];
    const float* b1     = (const float*)d_in[3];
    const float* gamma1 = (const float*)d_in[4];
    const float* beta1  = (const float*)d_in[5];
    const float* W2     = (const float*)d_in[6];
    const float* b2     = (const float*)d_in[7];
    const float* gamma2 = (const float*)d_in[8];
    const float* beta2  = (const float*)d_in[9];
    const float* Wl     = (const float*)d_in[10];
    const float* bl     = (const float*)d_in[11];

    const int H1   = in_sizes[3];               // 256
    const int H2   = in_sizes[7];               // 512
    const int DOUT = in_sizes[11];              // 128
    const int DIN  = in_sizes[2] / H1;          // 128
    const int N    = in_sizes[0] / DIN;         // 50000
    const long long E = in_sizes[1] / 2;        // 500000
    const float invM = 1.0f / (float)N;

    float *dinv, *agg1, *h1, *agg2, *h2;
    float2 *stats1, *stats2, *ss1, *ss2;
    int *cnt, *rowptr, *cursor, *flag;
    int2* adj;
    cudaGetSymbolAddress((void**)&dinv,   g_dinv);
    cudaGetSymbolAddress((void**)&cnt,    g_cnt);
    cudaGetSymbolAddress((void**)&rowptr, g_rowptr);
    cudaGetSymbolAddress((void**)&cursor, g_cursor);
    cudaGetSymbolAddress((void**)&adj,    g_adj);
    cudaGetSymbolAddress((void**)&agg1,   g_agg1);
    cudaGetSymbolAddress((void**)&h1,     g_h1);
    cudaGetSymbolAddress((void**)&agg2,   g_agg2);
    cudaGetSymbolAddress((void**)&h2,     g_h2);
    cudaGetSymbolAddress((void**)&stats1, g_stats1);
    cudaGetSymbolAddress((void**)&stats2, g_stats2);
    cudaGetSymbolAddress((void**)&ss1,    g_ss1);
    cudaGetSymbolAddress((void**)&ss2,    g_ss2);
    cudaGetSymbolAddress((void**)&flag,   g_flag32);

    float* out = (float*)d_out;

    // 1. CSR + norm prep
    k_init<<<(N + 255) / 256, 256>>>(cnt, N, flag, stats1, stats2, H1, H2);
    k_detect<<<1024, 256>>>((const int*)ei, E, flag);
    k_count<<<1024, 256>>>(ei, E, flag, cnt);
    k_scan<<<1, 1024>>>(cnt, rowptr, cursor, dinv, N);
    k_fill<<<1024, 256>>>(ei, E, flag, dinv, cursor, adj);

    int aggBlocks = (int)(((long long)N * 32 + 255) / 256);

    // 2. layer 1
    k_agg<128><<<aggBlocks, 256>>>(adj, rowptr, dinv, x, agg1, N);
    {
        dim3 grid(H1 / GBN, (N + GBM - 1) / GBM);
        k_gemm_tc<<<grid, 256>>>(agg1, W1, b1, h1, stats1, N, H1, DIN);
        k_bnprep<<<(H1 + 255) / 256, 256>>>(stats1, gamma1, beta1, ss1, H1, invM);
        long long h4 = (long long)N * H1 / 4;
        k_bnrelu<<<(int)((h4 + 255) / 256), 256>>>(h1, h4, H1 / 4, ss1);
    }

    // 3. layer 2
    k_agg<256><<<aggBlocks, 256>>>(adj, rowptr, dinv, h1, agg2, N);
    {
        dim3 grid(H2 / GBN, (N + GBM - 1) / GBM);
        k_gemm_tc<<<grid, 256>>>(agg2, W2, b2, h2, stats2, N, H2, H1);
        k_bnprep<<<(H2 + 255) / 256, 256>>>(stats2, gamma2, beta2, ss2, H2, invM);
        long long h4 = (long long)N * H2 / 4;
        k_bnrelu<<<(int)((h4 + 255) / 256), 256>>>(h2, h4, H2 / 4, ss2);
    }

    // 4. final projection
    {
        dim3 grid(DOUT / GBN, (N + GBM - 1) / GBM);
        k_gemm_tc<<<grid, 256>>>(h2, Wl, bl, out, nullptr, N, DOUT, H2);
    }
}

// round 4
// speedup vs baseline: 2.4756x; 1.1178x over previous
#include <cuda_runtime.h>
#include <cuda_bf16.h>
#include <cstdint>

// ---------------------------------------------------------------------------
// GCN encoder: N=50000, E=500000, 128 -> 256 -> 512 -> 128
// CSR gather aggregation (BN fused) + tf32 tensor-core GEMM (cp.async pipe)
// ---------------------------------------------------------------------------

#define MAXN 50048
#define MAXE 524288
#define EPS 1e-5f
#define SCAN_BLK 1024

__device__ float  g_dinv[MAXN];
__device__ int    g_cnt[MAXN];
__device__ int    g_rowptr[MAXN + 1];
__device__ int    g_cursor[MAXN];
__device__ int    g_bsum[64];
__device__ int2   g_adj[MAXE];                 // (src, bits(w))
__device__ float  g_agg1[(size_t)MAXN * 128];  // tf32-rounded
__device__ float  g_h1[(size_t)MAXN * 256];    // raw (pre-BN)
__device__ float  g_agg2[(size_t)MAXN * 256];  // tf32-rounded
__device__ float  g_h2[(size_t)MAXN * 512];    // raw (pre-BN)
__device__ float  g_w1[128 * 256];             // tf32-rounded weights
__device__ float  g_w2[256 * 512];
__device__ float2 g_stats1[256];               // (sum, sumsq)
__device__ float2 g_stats2[512];
__device__ float2 g_ss1[256];                  // (scale, shift)
__device__ float2 g_ss2[512];
__device__ int    g_flag32;                    // 1 => edge_index is int32 (zero-init, idempotent)

// ---------------------------------------------------------------------------

__device__ __forceinline__ void red_add_v2(float2* addr, float a, float b) {
    asm volatile("red.global.add.v2.f32 [%0], {%1,%2};"
                 :: "l"(addr), "f"(a), "f"(b) : "memory");
}

__device__ __forceinline__ int load_idx(const void* ei, long long pos, int is32) {
    if (is32) return ((const int*)ei)[pos];
    return (int)(((const long long*)ei)[pos]);
}

__device__ __forceinline__ uint32_t f2tf32(float f) {
    uint32_t u;
    asm("cvt.rna.tf32.f32 %0, %1;" : "=r"(u) : "f"(f));
    return u;
}

__device__ __forceinline__ void cp_async16(void* sptr, const void* gptr, int src_bytes) {
    uint32_t sa = (uint32_t)__cvta_generic_to_shared(sptr);
    asm volatile("cp.async.cg.shared.global [%0], [%1], 16, %2;"
                 :: "r"(sa), "l"(gptr), "r"(src_bytes));
}

// --- prep0: detect dtype, zero cnt + stats ----------------------------------
__global__ void k_prep0(const int* __restrict__ ei32, long long E,
                        int* cnt, int n, float2* st1, float2* st2,
                        int d1, int d2, int* flag) {
    long long i = blockIdx.x * (long long)blockDim.x + threadIdx.x;
    long long stride = (long long)gridDim.x * blockDim.x;
    int any = 0;
    for (long long j = i; j < E; j += stride)
        if (ei32[2 * j + 1] != 0) any = 1;
    if (any) atomicOr(flag, 1);
    if (i < n) cnt[i] = 0;
    if (i < d1) st1[i] = make_float2(0.f, 0.f);
    if (i < d2) st2[i] = make_float2(0.f, 0.f);
}

// --- in-degree counts ---------------------------------------------------------
__global__ void k_count(const void* ei, long long E, const int* flag, int* cnt) {
    long long i = blockIdx.x * (long long)blockDim.x + threadIdx.x;
    long long stride = (long long)gridDim.x * blockDim.x;
    int is32 = *flag;
    for (; i < E; i += stride) {
        int d = load_idx(ei, E + i, is32);
        atomicAdd(&cnt[d], 1);
    }
}

// --- 3-pass scan ----------------------------------------------------------------
__global__ __launch_bounds__(SCAN_BLK) void k_scan_red(const int* __restrict__ cnt,
                                                       int* __restrict__ bsum, int n) {
    int i = blockIdx.x * SCAN_BLK + threadIdx.x;
    int v = (i < n) ? cnt[i] : 0;
    int lane = threadIdx.x & 31, wid = threadIdx.x >> 5;
#pragma unroll
    for (int off = 16; off; off >>= 1) v += __shfl_xor_sync(0xffffffffu, v, off);
    __shared__ int ws[32];
    if (lane == 0) ws[wid] = v;
    __syncthreads();
    if (wid == 0) {
        v = ws[lane];
#pragma unroll
        for (int off = 16; off; off >>= 1) v += __shfl_xor_sync(0xffffffffu, v, off);
        if (lane == 0) bsum[blockIdx.x] = v;
    }
}

__global__ void k_scan_top(int* __restrict__ bsum, int nb,
                           int* __restrict__ rowptr, int n, int total) {
    int tid = threadIdx.x, lane = tid & 31, wid = tid >> 5;
    int v = (tid < nb) ? bsum[tid] : 0;
    int x = v;
#pragma unroll
    for (int off = 1; off < 32; off <<= 1) {
        int y = __shfl_up_sync(0xffffffffu, x, off);
        if (lane >= off) x += y;
    }
    __shared__ int ws[2];
    if (lane == 31) ws[wid] = x;
    __syncthreads();
    int excl = x - v + (wid == 1 ? ws[0] : 0);
    if (tid < nb) bsum[tid] = excl;
    if (tid == 0) rowptr[n] = total;
}

__global__ __launch_bounds__(SCAN_BLK) void k_scan_apply(const int* __restrict__ cnt,
                                                         const int* __restrict__ bsum,
                                                         int* __restrict__ rowptr,
                                                         int* __restrict__ cursor,
                                                         float* __restrict__ dinv, int n) {
    int i = blockIdx.x * SCAN_BLK + threadIdx.x;
    int v = (i < n) ? cnt[i] : 0;
    int lane = threadIdx.x & 31, wid = threadIdx.x >> 5;
    int x = v;
#pragma unroll
    for (int off = 1; off < 32; off <<= 1) {
        int y = __shfl_up_sync(0xffffffffu, x, off);
        if (lane >= off) x += y;
    }
    __shared__ int ws[32];
    if (lane == 31) ws[wid] = x;
    __syncthreads();
    if (wid == 0) {
        int w = ws[lane];
#pragma unroll
        for (int off = 1; off < 32; off <<= 1) {
            int y = __shfl_up_sync(0xffffffffu, w, off);
            if (lane >= off) w += y;
        }
        ws[lane] = w;
    }
    __syncthreads();
    int incl = x + (wid > 0 ? ws[wid - 1] : 0);
    int excl = incl - v + bsum[blockIdx.x];
    if (i < n) {
        rowptr[i] = excl;
        cursor[i] = excl;
        dinv[i] = rsqrtf((float)v + 1.0f);
    }
}

// --- bucket-fill adjacency -------------------------------------------------------
__global__ void k_fill(const void* __restrict__ ei, long long E, const int* flag,
                       const float* __restrict__ dinv, int* __restrict__ cursor,
                       int2* __restrict__ adj) {
    long long i = blockIdx.x * (long long)blockDim.x + threadIdx.x;
    long long stride = (long long)gridDim.x * blockDim.x;
    int is32 = *flag;
    for (; i < E; i += stride) {
        int s = load_idx(ei, i, is32);
        int d = load_idx(ei, E + i, is32);
        float w = dinv[s] * dinv[d];
        int pos = atomicAdd(&cursor[d], 1);
        adj[pos] = make_int2(s, __float_as_int(w));
    }
}

// --- weight pre-convert to tf32 ---------------------------------------------------
__global__ void k_cvtw(const float* __restrict__ W1, const float* __restrict__ W2,
                       float* __restrict__ o1, float* __restrict__ o2, int n1, int n2) {
    int i = blockIdx.x * blockDim.x + threadIdx.x;
    if (i < n1) o1[i] = __uint_as_float(f2tf32(W1[i]));
    if (i < n2) o2[i] = __uint_as_float(f2tf32(W2[i]));
}

// --- CSR aggregation, optional fused BN+ReLU on input, tf32-rounded output --------
template<int D, bool BN>
__global__ __launch_bounds__(256) void k_agg(const int2* __restrict__ adj,
                                             const int* __restrict__ rowptr,
                                             const float* __restrict__ dinv,
                                             const float* __restrict__ X,
                                             float* __restrict__ out, int N,
                                             const float2* __restrict__ ss) {
    int node = (blockIdx.x * blockDim.x + threadIdx.x) >> 5;
    int lane = threadIdx.x & 31;
    if (node >= N) return;
    constexpr int V = D / 128;
    float2 sr[V * 4];
    if (BN) {
#pragma unroll
        for (int v = 0; v < V; v++)
#pragma unroll
            for (int j = 0; j < 4; j++)
                sr[v * 4 + j] = ss[v * 128 + lane * 4 + j];
    }
    auto xf = [&](float4 a, int v) -> float4 {
        if (BN) {
            a.x = fmaxf(fmaf(a.x, sr[v*4+0].x, sr[v*4+0].y), 0.f);
            a.y = fmaxf(fmaf(a.y, sr[v*4+1].x, sr[v*4+1].y), 0.f);
            a.z = fmaxf(fmaf(a.z, sr[v*4+2].x, sr[v*4+2].y), 0.f);
            a.w = fmaxf(fmaf(a.w, sr[v*4+3].x, sr[v*4+3].y), 0.f);
        }
        return a;
    };
    float w0 = dinv[node]; w0 *= w0;
    const float4* xs = (const float4*)(X + (size_t)node * D);
    float4 acc[V];
#pragma unroll
    for (int v = 0; v < V; v++) {
        float4 a = xf(xs[v * 32 + lane], v);
        acc[v] = make_float4(a.x * w0, a.y * w0, a.z * w0, a.w * w0);
    }
    int j = rowptr[node], end = rowptr[node + 1];
    int2 e = (j < end) ? adj[j] : make_int2(0, 0);
    for (; j < end; j++) {
        int2 cur = e;
        if (j + 1 < end) e = adj[j + 1];
        float w = __int_as_float(cur.y);
        const float4* s = (const float4*)(X + (size_t)cur.x * D);
#pragma unroll
        for (int v = 0; v < V; v++) {
            float4 a = xf(s[v * 32 + lane], v);
            acc[v].x += w * a.x; acc[v].y += w * a.y;
            acc[v].z += w * a.z; acc[v].w += w * a.w;
        }
    }
    float4* o = (float4*)(out + (size_t)node * D);
#pragma unroll
    for (int v = 0; v < V; v++) {
        float4 a = acc[v];
        o[v * 32 + lane] = make_float4(__uint_as_float(f2tf32(a.x)),
                                       __uint_as_float(f2tf32(a.y)),
                                       __uint_as_float(f2tf32(a.z)),
                                       __uint_as_float(f2tf32(a.w)));
    }
}

// ---------------------------------------------------------------------------
// Pipelined tf32 GEMM (A, B already tf32-rounded): cp.async 2-stage.
// Block tile 128x128, 8 warps (32x64 each), BK=32. Fused bias + BN stats.
// ---------------------------------------------------------------------------
#define GBM 128
#define GBN 128
#define GBK 32
#define ASTRIDE 36
#define BSTRIDE 132
#define ASZ (GBM * ASTRIDE)
#define BSZ (GBK * BSTRIDE)
#define SMEM_PIPE ((2 * ASZ + 2 * BSZ) * 4)

__global__ __launch_bounds__(256) void k_gemm_pipe(const float* __restrict__ A,
                                                   const float* __restrict__ Bw,
                                                   const float* __restrict__ bias,
                                                   float* __restrict__ C,
                                                   float2* __restrict__ stats,
                                                   int M, int N, int K) {
    extern __shared__ float sm[];
    float* As = sm;
    float* Bs = sm + 2 * ASZ;

    const int tid  = threadIdx.x;
    const int lane = tid & 31;
    const int warpId = tid >> 5;
    const int warpM = warpId & 3;
    const int warpN = warpId >> 2;
    const int g = lane >> 2;
    const int t = lane & 3;
    const int bm = blockIdx.y * GBM;
    const int bn = blockIdx.x * GBN;

    const int a_row = tid >> 3;
    const int a_col = (tid & 7) * 4;
    const int b_k  = tid >> 5;
    const int b_n4 = (tid & 31) * 4;

    float4 acc[2][8];
#pragma unroll
    for (int i = 0; i < 2; i++)
#pragma unroll
        for (int j = 0; j < 8; j++)
            acc[i][j] = make_float4(0.f, 0.f, 0.f, 0.f);

    auto load_stage = [&](int stg, int k0) {
        float* pa = As + stg * ASZ;
        float* pb = Bs + stg * BSZ;
#pragma unroll
        for (int i = 0; i < 4; i++) {
            int row = i * 32 + a_row;
            int gm = bm + row;
            int ok = (gm < M) ? 16 : 0;
            int gmc = min(gm, M - 1);
            cp_async16(pa + row * ASTRIDE + a_col, A + (long long)gmc * K + k0 + a_col, ok);
        }
#pragma unroll
        for (int i = 0; i < 4; i++) {
            int kk = i * 8 + b_k;
            cp_async16(pb + kk * BSTRIDE + b_n4, Bw + (long long)(k0 + kk) * N + bn + b_n4, 16);
        }
    };

    const int nk = K / GBK;
    load_stage(0, 0);
    asm volatile("cp.async.commit_group;");

    for (int tk = 0; tk < nk; tk++) {
        if (tk + 1 < nk) {
            load_stage((tk + 1) & 1, (tk + 1) * GBK);
            asm volatile("cp.async.commit_group;");
            asm volatile("cp.async.wait_group 1;");
        } else {
            asm volatile("cp.async.wait_group 0;");
        }
        __syncthreads();

        const float* pa = As + (tk & 1) * ASZ;
        const float* pb = Bs + (tk & 1) * BSZ;
#pragma unroll
        for (int kk = 0; kk < GBK; kk += 8) {
            uint32_t afrag[2][4];
            uint32_t bfrag[8][2];
#pragma unroll
            for (int im = 0; im < 2; im++) {
                const float* base = pa + (warpM * 32 + im * 16 + g) * ASTRIDE + kk + t;
                afrag[im][0] = __float_as_uint(base[0]);
                afrag[im][1] = __float_as_uint(base[8 * ASTRIDE]);
                afrag[im][2] = __float_as_uint(base[4]);
                afrag[im][3] = __float_as_uint(base[8 * ASTRIDE + 4]);
            }
#pragma unroll
            for (int jn = 0; jn < 8; jn++) {
                int n = warpN * 64 + jn * 8 + g;
                bfrag[jn][0] = __float_as_uint(pb[(kk + t) * BSTRIDE + n]);
                bfrag[jn][1] = __float_as_uint(pb[(kk + t + 4) * BSTRIDE + n]);
            }
#pragma unroll
            for (int im = 0; im < 2; im++)
#pragma unroll
                for (int jn = 0; jn < 8; jn++) {
                    float4& c = acc[im][jn];
                    asm volatile(
                        "mma.sync.aligned.m16n8k8.row.col.f32.tf32.tf32.f32 "
                        "{%0,%1,%2,%3}, {%4,%5,%6,%7}, {%8,%9}, {%0,%1,%2,%3};"
                        : "+f"(c.x), "+f"(c.y), "+f"(c.z), "+f"(c.w)
                        : "r"(afrag[im][0]), "r"(afrag[im][1]),
                          "r"(afrag[im][2]), "r"(afrag[im][3]),
                          "r"(bfrag[jn][0]), "r"(bfrag[jn][1]));
                }
        }
        __syncthreads();
    }

#pragma unroll
    for (int jn = 0; jn < 8; jn++) {
        int col = bn + warpN * 64 + jn * 8 + 2 * t;
        float bx = bias[col], by = bias[col + 1];
        float s0 = 0.f, q0 = 0.f, s1 = 0.f, q1 = 0.f;
#pragma unroll
        for (int im = 0; im < 2; im++) {
            int row0 = bm + warpM * 32 + im * 16 + g;
            float4 c = acc[im][jn];
            if (row0 < M) {
                float ox = c.x + bx, oy = c.y + by;
                *(float2*)(C + (long long)row0 * N + col) = make_float2(ox, oy);
                s0 += ox; q0 += ox * ox; s1 += oy; q1 += oy * oy;
            }
            if (row0 + 8 < M) {
                float oz = c.z + bx, ow = c.w + by;
                *(float2*)(C + (long long)(row0 + 8) * N + col) = make_float2(oz, ow);
                s0 += oz; q0 += oz * oz; s1 += ow; q1 += ow * ow;
            }
        }
#pragma unroll
        for (int m = 4; m < 32; m <<= 1) {
            s0 += __shfl_xor_sync(0xffffffffu, s0, m);
            q0 += __shfl_xor_sync(0xffffffffu, q0, m);
            s1 += __shfl_xor_sync(0xffffffffu, s1, m);
            q1 += __shfl_xor_sync(0xffffffffu, q1, m);
        }
        if (g == 0) {
            red_add_v2(&stats[col], s0, q0);
            red_add_v2(&stats[col + 1], s1, q1);
        }
    }
}

// ---------------------------------------------------------------------------
// Final GEMM: A = raw h2 with fused BN2+ReLU (per-K-column scale/shift) + cvt,
// B = raw Wl + cvt. Sync loads (transform in load path). No stats.
// ---------------------------------------------------------------------------
__global__ __launch_bounds__(256) void k_gemm_fin(const float* __restrict__ A,
                                                  const float* __restrict__ Bw,
                                                  const float* __restrict__ bias,
                                                  float* __restrict__ C,
                                                  const float2* __restrict__ ssA,
                                                  int M, int N, int K) {
    __shared__ float As[ASZ];
    __shared__ float Bs[BSZ];

    const int tid  = threadIdx.x;
    const int lane = tid & 31;
    const int warpId = tid >> 5;
    const int warpM = warpId & 3;
    const int warpN = warpId >> 2;
    const int g = lane >> 2;
    const int t = lane & 3;
    const int bm = blockIdx.y * GBM;
    const int bn = blockIdx.x * GBN;

    float4 acc[2][8];
#pragma unroll
    for (int i = 0; i < 2; i++)
#pragma unroll
        for (int j = 0; j < 8; j++)
            acc[i][j] = make_float4(0.f, 0.f, 0.f, 0.f);

    const int a_row = tid >> 3;
    const int a_col = (tid & 7) * 4;
    const int b_k  = tid >> 5;
    const int b_n4 = (tid & 31) * 4;

    for (int k0 = 0; k0 < K; k0 += GBK) {
#pragma unroll
        for (int i = 0; i < 4; i++) {
            int row = i * 32 + a_row;
            int gm = bm + row;
            float4 v = make_float4(0.f, 0.f, 0.f, 0.f);
            if (gm < M) v = *(const float4*)(A + (long long)gm * K + k0 + a_col);
            float2 c0 = ssA[k0 + a_col + 0];
            float2 c1 = ssA[k0 + a_col + 1];
            float2 c2 = ssA[k0 + a_col + 2];
            float2 c3 = ssA[k0 + a_col + 3];
            v.x = fmaxf(fmaf(v.x, c0.x, c0.y), 0.f);
            v.y = fmaxf(fmaf(v.y, c1.x, c1.y), 0.f);
            v.z = fmaxf(fmaf(v.z, c2.x, c2.y), 0.f);
            v.w = fmaxf(fmaf(v.w, c3.x, c3.y), 0.f);
            float* p = As + row * ASTRIDE + a_col;
            p[0] = __uint_as_float(f2tf32(v.x));
            p[1] = __uint_as_float(f2tf32(v.y));
            p[2] = __uint_as_float(f2tf32(v.z));
            p[3] = __uint_as_float(f2tf32(v.w));
        }
#pragma unroll
        for (int i = 0; i < 4; i++) {
            int kk = i * 8 + b_k;
            float4 v = *(const float4*)(Bw + (long long)(k0 + kk) * N + bn + b_n4);
            float* p = Bs + kk * BSTRIDE + b_n4;
            p[0] = __uint_as_float(f2tf32(v.x));
            p[1] = __uint_as_float(f2tf32(v.y));
            p[2] = __uint_as_float(f2tf32(v.z));
            p[3] = __uint_as_float(f2tf32(v.w));
        }
        __syncthreads();

#pragma unroll
        for (int kk = 0; kk < GBK; kk += 8) {
            uint32_t afrag[2][4];
            uint32_t bfrag[8][2];
#pragma unroll
            for (int im = 0; im < 2; im++) {
                const float* base = As + (warpM * 32 + im * 16 + g) * ASTRIDE + kk + t;
                afrag[im][0] = __float_as_uint(base[0]);
                afrag[im][1] = __float_as_uint(base[8 * ASTRIDE]);
                afrag[im][2] = __float_as_uint(base[4]);
                afrag[im][3] = __float_as_uint(base[8 * ASTRIDE + 4]);
            }
#pragma unroll
            for (int jn = 0; jn < 8; jn++) {
                int n = warpN * 64 + jn * 8 + g;
                bfrag[jn][0] = __float_as_uint(Bs[(kk + t) * BSTRIDE + n]);
                bfrag[jn][1] = __float_as_uint(Bs[(kk + t + 4) * BSTRIDE + n]);
            }
#pragma unroll
            for (int im = 0; im < 2; im++)
#pragma unroll
                for (int jn = 0; jn < 8; jn++) {
                    float4& c = acc[im][jn];
                    asm volatile(
                        "mma.sync.aligned.m16n8k8.row.col.f32.tf32.tf32.f32 "
                        "{%0,%1,%2,%3}, {%4,%5,%6,%7}, {%8,%9}, {%0,%1,%2,%3};"
                        : "+f"(c.x), "+f"(c.y), "+f"(c.z), "+f"(c.w)
                        : "r"(afrag[im][0]), "r"(afrag[im][1]),
                          "r"(afrag[im][2]), "r"(afrag[im][3]),
                          "r"(bfrag[jn][0]), "r"(bfrag[jn][1]));
                }
        }
        __syncthreads();
    }

#pragma unroll
    for (int jn = 0; jn < 8; jn++) {
        int col = bn + warpN * 64 + jn * 8 + 2 * t;
        float bx = bias[col], by = bias[col + 1];
#pragma unroll
        for (int im = 0; im < 2; im++) {
            int row0 = bm + warpM * 32 + im * 16 + g;
            float4 c = acc[im][jn];
            if (row0 < M)
                *(float2*)(C + (long long)row0 * N + col) = make_float2(c.x + bx, c.y + by);
            if (row0 + 8 < M)
                *(float2*)(C + (long long)(row0 + 8) * N + col) = make_float2(c.z + bx, c.w + by);
        }
    }
}

// --- stats -> per-col (scale, shift) ------------------------------------------
__global__ void k_bnprep(const float2* __restrict__ stats,
                         const float* __restrict__ gamma,
                         const float* __restrict__ beta,
                         float2* __restrict__ ss, int D, float invM) {
    int c = blockIdx.x * blockDim.x + threadIdx.x;
    if (c < D) {
        float mu = stats[c].x * invM;
        float var = stats[c].y * invM - mu * mu;
        float sc = gamma[c] * rsqrtf(var + EPS);
        ss[c] = make_float2(sc, beta[c] - mu * sc);
    }
}

// ---------------------------------------------------------------------------

extern "C" void kernel_launch(void* const* d_in, const int* in_sizes, int n_in,
                              void* d_out, int out_size) {
    const float* x      = (const float*)d_in[0];
    const void*  ei     = d_in[1];
    const float* W1     = (const float*)d_in[2];
    const float* b1     = (const float*)d_in[3];
    const float* gamma1 = (const float*)d_in[4];
    const float* beta1  = (const float*)d_in[5];
    const float* W2     = (const float*)d_in[6];
    const float* b2     = (const float*)d_in[7];
    const float* gamma2 = (const float*)d_in[8];
    const float* beta2  = (const float*)d_in[9];
    const float* Wl     = (const float*)d_in[10];
    const float* bl     = (const float*)d_in[11];

    const int H1   = in_sizes[3];               // 256
    const int H2   = in_sizes[7];               // 512
    const int DOUT = in_sizes[11];              // 128
    const int DIN  = in_sizes[2] / H1;          // 128
    const int N    = in_sizes[0] / DIN;         // 50000
    const long long E = in_sizes[1] / 2;        // 500000
    const float invM = 1.0f / (float)N;

    float *dinv, *agg1, *h1, *agg2, *h2, *w1, *w2;
    float2 *stats1, *stats2, *ss1, *ss2;
    int *cnt, *rowptr, *cursor, *flag, *bsum;
    int2* adj;
    cudaGetSymbolAddress((void**)&dinv,   g_dinv);
    cudaGetSymbolAddress((void**)&cnt,    g_cnt);
    cudaGetSymbolAddress((void**)&rowptr, g_rowptr);
    cudaGetSymbolAddress((void**)&cursor, g_cursor);
    cudaGetSymbolAddress((void**)&bsum,   g_bsum);
    cudaGetSymbolAddress((void**)&adj,    g_adj);
    cudaGetSymbolAddress((void**)&agg1,   g_agg1);
    cudaGetSymbolAddress((void**)&h1,     g_h1);
    cudaGetSymbolAddress((void**)&agg2,   g_agg2);
    cudaGetSymbolAddress((void**)&h2,     g_h2);
    cudaGetSymbolAddress((void**)&w1,     g_w1);
    cudaGetSymbolAddress((void**)&w2,     g_w2);
    cudaGetSymbolAddress((void**)&stats1, g_stats1);
    cudaGetSymbolAddress((void**)&stats2, g_stats2);
    cudaGetSymbolAddress((void**)&ss1,    g_ss1);
    cudaGetSymbolAddress((void**)&ss2,    g_ss2);
    cudaGetSymbolAddress((void**)&flag,   g_flag32);

    float* out = (float*)d_out;

    cudaFuncSetAttribute(k_gemm_pipe, cudaFuncAttributeMaxDynamicSharedMemorySize, SMEM_PIPE);

    const int scanBlocks = (N + SCAN_BLK - 1) / SCAN_BLK;

    // 1. prep: dtype detect + zero, count, scan, fill, weight cvt
    k_prep0<<<512, 256>>>((const int*)ei, E, cnt, N, stats1, stats2, H1, H2, flag);
    k_count<<<1024, 256>>>(ei, E, flag, cnt);
    k_scan_red<<<scanBlocks, SCAN_BLK>>>(cnt, bsum, N);
    k_scan_top<<<1, 64>>>(bsum, scanBlocks, rowptr, N, (int)E);
    k_scan_apply<<<scanBlocks, SCAN_BLK>>>(cnt, bsum, rowptr, cursor, dinv, N);
    k_fill<<<1024, 256>>>(ei, E, flag, dinv, cursor, adj);
    k_cvtw<<<(H1 * H2 + 255) / 256, 256>>>(W1, W2, w1, w2, DIN * H1, H1 * H2);

    const int aggBlocks = (int)(((long long)N * 32 + 255) / 256);

    // 2. layer 1: agg1 = A x (tf32) ; h1 = agg1 @ W1 + b1 (stats fused)
    k_agg<128, false><<<aggBlocks, 256>>>(adj, rowptr, dinv, x, agg1, N, nullptr);
    {
        dim3 grid(H1 / GBN, (N + GBM - 1) / GBM);
        k_gemm_pipe<<<grid, 256, SMEM_PIPE>>>(agg1, w1, b1, h1, stats1, N, H1, DIN);
        k_bnprep<<<(H1 + 255) / 256, 256>>>(stats1, gamma1, beta1, ss1, H1, invM);
    }

    // 3. layer 2: agg2 = A bnrelu(h1) (fused, tf32) ; h2 = agg2 @ W2 + b2
    k_agg<256, true><<<aggBlocks, 256>>>(adj, rowptr, dinv, h1, agg2, N, ss1);
    {
        dim3 grid(H2 / GBN, (N + GBM - 1) / GBM);
        k_gemm_pipe<<<grid, 256, SMEM_PIPE>>>(agg2, w2, b2, h2, stats2, N, H2, H1);
        k_bnprep<<<(H2 + 255) / 256, 256>>>(stats2, gamma2, beta2, ss2, H2, invM);
    }

    // 4. final projection: out = bnrelu(h2) @ Wl + bl (BN fused into A load)
    {
        dim3 grid(DOUT / GBN, (N + GBM - 1) / GBM);
        k_gemm_fin<<<grid, 256>>>(h2, Wl, bl, out, ss2, N, DOUT, H2);
    }
}

// round 5
// speedup vs baseline: 2.6314x; 1.0629x over previous
#include <cuda_runtime.h>
#include <cuda_bf16.h>
#include <cstdint>

// ---------------------------------------------------------------------------
// GCN encoder: N=50000, E=500000, 128 -> 256 -> 512 -> 128
// CSR gather aggregation (BN fused) + tf32 tensor-core GEMM (cp.async pipe)
// ---------------------------------------------------------------------------

#define MAXN 50048
#define MAXE 524288
#define EPS 1e-5f
#define SCAN_BLK 1024

__device__ float  g_dinv[MAXN];
__device__ int    g_cnt[MAXN];
__device__ int    g_rowptr[MAXN + 1];
__device__ int    g_cursor[MAXN];
__device__ int    g_bsum[64];
__device__ int2   g_adj[MAXE];                 // (src, bits(w))
__device__ float  g_agg1[(size_t)MAXN * 128];  // tf32-rounded
__device__ float  g_h1[(size_t)MAXN * 256];    // raw (pre-BN)
__device__ float  g_agg2[(size_t)MAXN * 256];  // tf32-rounded
__device__ float  g_h2[(size_t)MAXN * 512];    // raw (pre-BN)
__device__ float  g_w1[128 * 256];             // tf32-rounded weights
__device__ float  g_w2[256 * 512];
__device__ float  g_wl[512 * 128];
__device__ float2 g_stats1[256];               // (sum, sumsq)
__device__ float2 g_stats2[512];
__device__ float2 g_ss1[256];                  // (scale, shift)
__device__ float2 g_ss2[512];
__device__ int    g_flag32;                    // 1 => edge_index is int32 (zero-init, idempotent)

// ---------------------------------------------------------------------------

__device__ __forceinline__ void red_add_v2(float2* addr, float a, float b) {
    asm volatile("red.global.add.v2.f32 [%0], {%1,%2};"
                 :: "l"(addr), "f"(a), "f"(b) : "memory");
}

__device__ __forceinline__ int load_idx(const void* ei, long long pos, int is32) {
    if (is32) return ((const int*)ei)[pos];
    return (int)(((const long long*)ei)[pos]);
}

__device__ __forceinline__ uint32_t f2tf32(float f) {
    uint32_t u;
    asm("cvt.rna.tf32.f32 %0, %1;" : "=r"(u) : "f"(f));
    return u;
}

__device__ __forceinline__ void cp_async16(void* sptr, const void* gptr, int src_bytes) {
    uint32_t sa = (uint32_t)__cvta_generic_to_shared(sptr);
    asm volatile("cp.async.cg.shared.global [%0], [%1], 16, %2;"
                 :: "r"(sa), "l"(gptr), "r"(src_bytes));
}

// --- dtype detect: sample first <=8192 edges; int64 => odd words all zero ---
__global__ void k_detect(const int* __restrict__ ei32, long long E, int* flag) {
    long long lim = E < 8192 ? E : 8192;
    int any = 0;
    for (long long j = threadIdx.x; j < lim; j += blockDim.x)
        if (ei32[2 * j + 1] != 0) any = 1;
    if (any) atomicOr(flag, 1);
}

// --- prep0: zero cnt + stats --------------------------------------------------
__global__ void k_prep0(int* cnt, int n, float2* st1, float2* st2, int d1, int d2) {
    int i = blockIdx.x * blockDim.x + threadIdx.x;
    if (i < n) cnt[i] = 0;
    if (i < d1) st1[i] = make_float2(0.f, 0.f);
    if (i < d2) st2[i] = make_float2(0.f, 0.f);
}

// --- in-degree counts ---------------------------------------------------------
__global__ void k_count(const void* ei, long long E, const int* flag, int* cnt) {
    long long i = blockIdx.x * (long long)blockDim.x + threadIdx.x;
    long long stride = (long long)gridDim.x * blockDim.x;
    int is32 = *flag;
    for (; i < E; i += stride) {
        int d = load_idx(ei, E + i, is32);
        atomicAdd(&cnt[d], 1);
    }
}

// --- 3-pass scan ----------------------------------------------------------------
__global__ __launch_bounds__(SCAN_BLK) void k_scan_red(const int* __restrict__ cnt,
                                                       int* __restrict__ bsum, int n) {
    int i = blockIdx.x * SCAN_BLK + threadIdx.x;
    int v = (i < n) ? cnt[i] : 0;
    int lane = threadIdx.x & 31, wid = threadIdx.x >> 5;
#pragma unroll
    for (int off = 16; off; off >>= 1) v += __shfl_xor_sync(0xffffffffu, v, off);
    __shared__ int ws[32];
    if (lane == 0) ws[wid] = v;
    __syncthreads();
    if (wid == 0) {
        v = ws[lane];
#pragma unroll
        for (int off = 16; off; off >>= 1) v += __shfl_xor_sync(0xffffffffu, v, off);
        if (lane == 0) bsum[blockIdx.x] = v;
    }
}

__global__ void k_scan_top(int* __restrict__ bsum, int nb,
                           int* __restrict__ rowptr, int n, int total) {
    int tid = threadIdx.x, lane = tid & 31, wid = tid >> 5;
    int v = (tid < nb) ? bsum[tid] : 0;
    int x = v;
#pragma unroll
    for (int off = 1; off < 32; off <<= 1) {
        int y = __shfl_up_sync(0xffffffffu, x, off);
        if (lane >= off) x += y;
    }
    __shared__ int ws[2];
    if (lane == 31) ws[wid] = x;
    __syncthreads();
    int excl = x - v + (wid == 1 ? ws[0] : 0);
    if (tid < nb) bsum[tid] = excl;
    if (tid == 0) rowptr[n] = total;
}

__global__ __launch_bounds__(SCAN_BLK) void k_scan_apply(const int* __restrict__ cnt,
                                                         const int* __restrict__ bsum,
                                                         int* __restrict__ rowptr,
                                                         int* __restrict__ cursor,
                                                         float* __restrict__ dinv, int n) {
    int i = blockIdx.x * SCAN_BLK + threadIdx.x;
    int v = (i < n) ? cnt[i] : 0;
    int lane = threadIdx.x & 31, wid = threadIdx.x >> 5;
    int x = v;
#pragma unroll
    for (int off = 1; off < 32; off <<= 1) {
        int y = __shfl_up_sync(0xffffffffu, x, off);
        if (lane >= off) x += y;
    }
    __shared__ int ws[32];
    if (lane == 31) ws[wid] = x;
    __syncthreads();
    if (wid == 0) {
        int w = ws[lane];
#pragma unroll
        for (int off = 1; off < 32; off <<= 1) {
            int y = __shfl_up_sync(0xffffffffu, w, off);
            if (lane >= off) w += y;
        }
        ws[lane] = w;
    }
    __syncthreads();
    int incl = x + (wid > 0 ? ws[wid - 1] : 0);
    int excl = incl - v + bsum[blockIdx.x];
    if (i < n) {
        rowptr[i] = excl;
        cursor[i] = excl;
        dinv[i] = rsqrtf((float)v + 1.0f);
    }
}

// --- bucket-fill adjacency -------------------------------------------------------
__global__ void k_fill(const void* __restrict__ ei, long long E, const int* flag,
                       const float* __restrict__ dinv, int* __restrict__ cursor,
                       int2* __restrict__ adj) {
    long long i = blockIdx.x * (long long)blockDim.x + threadIdx.x;
    long long stride = (long long)gridDim.x * blockDim.x;
    int is32 = *flag;
    for (; i < E; i += stride) {
        int s = load_idx(ei, i, is32);
        int d = load_idx(ei, E + i, is32);
        float w = dinv[s] * dinv[d];
        int pos = atomicAdd(&cursor[d], 1);
        adj[pos] = make_int2(s, __float_as_int(w));
    }
}

// --- weight pre-convert to tf32 ---------------------------------------------------
__global__ void k_cvtw(const float* __restrict__ W1, const float* __restrict__ W2,
                       const float* __restrict__ W3,
                       float* __restrict__ o1, float* __restrict__ o2,
                       float* __restrict__ o3, int n1, int n2, int n3) {
    int i = blockIdx.x * blockDim.x + threadIdx.x;
    if (i < n1) o1[i] = __uint_as_float(f2tf32(W1[i]));
    if (i < n2) o2[i] = __uint_as_float(f2tf32(W2[i]));
    if (i < n3) o3[i] = __uint_as_float(f2tf32(W3[i]));
}

// --- CSR aggregation, optional fused BN+ReLU on input, tf32-rounded output --------
template<int D, bool BN>
__global__ __launch_bounds__(256) void k_agg(const int2* __restrict__ adj,
                                             const int* __restrict__ rowptr,
                                             const float* __restrict__ dinv,
                                             const float* __restrict__ X,
                                             float* __restrict__ out, int N,
                                             const float2* __restrict__ ss) {
    int node = (blockIdx.x * blockDim.x + threadIdx.x) >> 5;
    int lane = threadIdx.x & 31;
    if (node >= N) return;
    constexpr int V = D / 128;
    float2 sr[V * 4];
    if (BN) {
#pragma unroll
        for (int v = 0; v < V; v++)
#pragma unroll
            for (int j = 0; j < 4; j++)
                sr[v * 4 + j] = ss[v * 128 + lane * 4 + j];
    }
    auto xf = [&](float4 a, int v) -> float4 {
        if (BN) {
            a.x = fmaxf(fmaf(a.x, sr[v*4+0].x, sr[v*4+0].y), 0.f);
            a.y = fmaxf(fmaf(a.y, sr[v*4+1].x, sr[v*4+1].y), 0.f);
            a.z = fmaxf(fmaf(a.z, sr[v*4+2].x, sr[v*4+2].y), 0.f);
            a.w = fmaxf(fmaf(a.w, sr[v*4+3].x, sr[v*4+3].y), 0.f);
        }
        return a;
    };
    float w0 = dinv[node]; w0 *= w0;
    const float4* xs = (const float4*)(X + (size_t)node * D);
    float4 acc[V];
#pragma unroll
    for (int v = 0; v < V; v++) {
        float4 a = xf(xs[v * 32 + lane], v);
        acc[v] = make_float4(a.x * w0, a.y * w0, a.z * w0, a.w * w0);
    }
    int j = rowptr[node], end = rowptr[node + 1];
    int2 e = (j < end) ? adj[j] : make_int2(0, 0);
    for (; j < end; j++) {
        int2 cur = e;
        if (j + 1 < end) e = adj[j + 1];
        float w = __int_as_float(cur.y);
        const float4* s = (const float4*)(X + (size_t)cur.x * D);
#pragma unroll
        for (int v = 0; v < V; v++) {
            float4 a = xf(s[v * 32 + lane], v);
            acc[v].x += w * a.x; acc[v].y += w * a.y;
            acc[v].z += w * a.z; acc[v].w += w * a.w;
        }
    }
    float4* o = (float4*)(out + (size_t)node * D);
#pragma unroll
    for (int v = 0; v < V; v++) {
        float4 a = acc[v];
        o[v * 32 + lane] = make_float4(__uint_as_float(f2tf32(a.x)),
                                       __uint_as_float(f2tf32(a.y)),
                                       __uint_as_float(f2tf32(a.z)),
                                       __uint_as_float(f2tf32(a.w)));
    }
}

// ---------------------------------------------------------------------------
// Pipelined tf32 GEMM (A, B already tf32-rounded): cp.async 2-stage.
// Block tile 128x128, 8 warps (32x64 each), BK=32. Fused bias + BN stats.
// ---------------------------------------------------------------------------
#define GBM 128
#define GBN 128
#define GBK 32
#define ASTRIDE 36
#define BSTRIDE 132
#define ASZ (GBM * ASTRIDE)
#define BSZ (GBK * BSTRIDE)
#define SMEM_PIPE ((2 * ASZ + 2 * BSZ) * 4)
#define SMEM_FIN  (SMEM_PIPE + 512 * 8)

__global__ __launch_bounds__(256) void k_gemm_pipe(const float* __restrict__ A,
                                                   const float* __restrict__ Bw,
                                                   const float* __restrict__ bias,
                                                   float* __restrict__ C,
                                                   float2* __restrict__ stats,
                                                   int M, int N, int K) {
    extern __shared__ float sm[];
    float* As = sm;
    float* Bs = sm + 2 * ASZ;

    const int tid  = threadIdx.x;
    const int lane = tid & 31;
    const int warpId = tid >> 5;
    const int warpM = warpId & 3;
    const int warpN = warpId >> 2;
    const int g = lane >> 2;
    const int t = lane & 3;
    const int bm = blockIdx.y * GBM;
    const int bn = blockIdx.x * GBN;

    const int a_row = tid >> 3;
    const int a_col = (tid & 7) * 4;
    const int b_k  = tid >> 5;
    const int b_n4 = (tid & 31) * 4;

    float4 acc[2][8];
#pragma unroll
    for (int i = 0; i < 2; i++)
#pragma unroll
        for (int j = 0; j < 8; j++)
            acc[i][j] = make_float4(0.f, 0.f, 0.f, 0.f);

    auto load_stage = [&](int stg, int k0) {
        float* pa = As + stg * ASZ;
        float* pb = Bs + stg * BSZ;
#pragma unroll
        for (int i = 0; i < 4; i++) {
            int row = i * 32 + a_row;
            int gm = bm + row;
            int ok = (gm < M) ? 16 : 0;
            int gmc = min(gm, M - 1);
            cp_async16(pa + row * ASTRIDE + a_col, A + (long long)gmc * K + k0 + a_col, ok);
        }
#pragma unroll
        for (int i = 0; i < 4; i++) {
            int kk = i * 8 + b_k;
            cp_async16(pb + kk * BSTRIDE + b_n4, Bw + (long long)(k0 + kk) * N + bn + b_n4, 16);
        }
    };

    const int nk = K / GBK;
    load_stage(0, 0);
    asm volatile("cp.async.commit_group;");

    for (int tk = 0; tk < nk; tk++) {
        if (tk + 1 < nk) {
            load_stage((tk + 1) & 1, (tk + 1) * GBK);
            asm volatile("cp.async.commit_group;");
            asm volatile("cp.async.wait_group 1;");
        } else {
            asm volatile("cp.async.wait_group 0;");
        }
        __syncthreads();

        const float* pa = As + (tk & 1) * ASZ;
        const float* pb = Bs + (tk & 1) * BSZ;
#pragma unroll
        for (int kk = 0; kk < GBK; kk += 8) {
            uint32_t afrag[2][4];
            uint32_t bfrag[8][2];
#pragma unroll
            for (int im = 0; im < 2; im++) {
                const float* base = pa + (warpM * 32 + im * 16 + g) * ASTRIDE + kk + t;
                afrag[im][0] = __float_as_uint(base[0]);
                afrag[im][1] = __float_as_uint(base[8 * ASTRIDE]);
                afrag[im][2] = __float_as_uint(base[4]);
                afrag[im][3] = __float_as_uint(base[8 * ASTRIDE + 4]);
            }
#pragma unroll
            for (int jn = 0; jn < 8; jn++) {
                int n = warpN * 64 + jn * 8 + g;
                bfrag[jn][0] = __float_as_uint(pb[(kk + t) * BSTRIDE + n]);
                bfrag[jn][1] = __float_as_uint(pb[(kk + t + 4) * BSTRIDE + n]);
            }
#pragma unroll
            for (int im = 0; im < 2; im++)
#pragma unroll
                for (int jn = 0; jn < 8; jn++) {
                    float4& c = acc[im][jn];
                    asm volatile(
                        "mma.sync.aligned.m16n8k8.row.col.f32.tf32.tf32.f32 "
                        "{%0,%1,%2,%3}, {%4,%5,%6,%7}, {%8,%9}, {%0,%1,%2,%3};"
                        : "+f"(c.x), "+f"(c.y), "+f"(c.z), "+f"(c.w)
                        : "r"(afrag[im][0]), "r"(afrag[im][1]),
                          "r"(afrag[im][2]), "r"(afrag[im][3]),
                          "r"(bfrag[jn][0]), "r"(bfrag[jn][1]));
                }
        }
        __syncthreads();
    }

#pragma unroll
    for (int jn = 0; jn < 8; jn++) {
        int col = bn + warpN * 64 + jn * 8 + 2 * t;
        float bx = bias[col], by = bias[col + 1];
        float s0 = 0.f, q0 = 0.f, s1 = 0.f, q1 = 0.f;
#pragma unroll
        for (int im = 0; im < 2; im++) {
            int row0 = bm + warpM * 32 + im * 16 + g;
            float4 c = acc[im][jn];
            if (row0 < M) {
                float ox = c.x + bx, oy = c.y + by;
                *(float2*)(C + (long long)row0 * N + col) = make_float2(ox, oy);
                s0 += ox; q0 += ox * ox; s1 += oy; q1 += oy * oy;
            }
            if (row0 + 8 < M) {
                float oz = c.z + bx, ow = c.w + by;
                *(float2*)(C + (long long)(row0 + 8) * N + col) = make_float2(oz, ow);
                s0 += oz; q0 += oz * oz; s1 += ow; q1 += ow * ow;
            }
        }
#pragma unroll
        for (int m = 4; m < 32; m <<= 1) {
            s0 += __shfl_xor_sync(0xffffffffu, s0, m);
            q0 += __shfl_xor_sync(0xffffffffu, q0, m);
            s1 += __shfl_xor_sync(0xffffffffu, s1, m);
            q1 += __shfl_xor_sync(0xffffffffu, q1, m);
        }
        if (g == 0) {
            red_add_v2(&stats[col], s0, q0);
            red_add_v2(&stats[col + 1], s1, q1);
        }
    }
}

// ---------------------------------------------------------------------------
// Final GEMM, pipelined: A = raw h2 (BN2+ReLU+cvt applied at frag build),
// B = pre-converted tf32 Wl. No stats.
// ---------------------------------------------------------------------------
__global__ __launch_bounds__(256) void k_gemm_fin(const float* __restrict__ A,
                                                  const float* __restrict__ Bw,
                                                  const float* __restrict__ bias,
                                                  float* __restrict__ C,
                                                  const float2* __restrict__ ssA,
                                                  int M, int N, int K) {
    extern __shared__ float sm[];
    float* As = sm;
    float* Bs = sm + 2 * ASZ;
    float2* ssm = (float2*)(sm + 2 * ASZ + 2 * BSZ);

    const int tid  = threadIdx.x;
    const int lane = tid & 31;
    const int warpId = tid >> 5;
    const int warpM = warpId & 3;
    const int warpN = warpId >> 2;
    const int g = lane >> 2;
    const int t = lane & 3;
    const int bm = blockIdx.y * GBM;
    const int bn = blockIdx.x * GBN;

    // stage BN (scale, shift) for all K columns
    for (int c = tid; c < K; c += 256) ssm[c] = ssA[c];

    const int a_row = tid >> 3;
    const int a_col = (tid & 7) * 4;
    const int b_k  = tid >> 5;
    const int b_n4 = (tid & 31) * 4;

    float4 acc[2][8];
#pragma unroll
    for (int i = 0; i < 2; i++)
#pragma unroll
        for (int j = 0; j < 8; j++)
            acc[i][j] = make_float4(0.f, 0.f, 0.f, 0.f);

    auto load_stage = [&](int stg, int k0) {
        float* pa = As + stg * ASZ;
        float* pb = Bs + stg * BSZ;
#pragma unroll
        for (int i = 0; i < 4; i++) {
            int row = i * 32 + a_row;
            int gm = bm + row;
            int ok = (gm < M) ? 16 : 0;
            int gmc = min(gm, M - 1);
            cp_async16(pa + row * ASTRIDE + a_col, A + (long long)gmc * K + k0 + a_col, ok);
        }
#pragma unroll
        for (int i = 0; i < 4; i++) {
            int kk = i * 8 + b_k;
            cp_async16(pb + kk * BSTRIDE + b_n4, Bw + (long long)(k0 + kk) * N + bn + b_n4, 16);
        }
    };

    const int nk = K / GBK;
    load_stage(0, 0);
    asm volatile("cp.async.commit_group;");

    for (int tk = 0; tk < nk; tk++) {
        if (tk + 1 < nk) {
            load_stage((tk + 1) & 1, (tk + 1) * GBK);
            asm volatile("cp.async.commit_group;");
            asm volatile("cp.async.wait_group 1;");
        } else {
            asm volatile("cp.async.wait_group 0;");
        }
        __syncthreads();

        const float* pa = As + (tk & 1) * ASZ;
        const float* pb = Bs + (tk & 1) * BSZ;
        const int kbase = tk * GBK;
#pragma unroll
        for (int kk = 0; kk < GBK; kk += 8) {
            float2 c0 = ssm[kbase + kk + t];
            float2 c1 = ssm[kbase + kk + t + 4];
            uint32_t afrag[2][4];
            uint32_t bfrag[8][2];
#pragma unroll
            for (int im = 0; im < 2; im++) {
                const float* base = pa + (warpM * 32 + im * 16 + g) * ASTRIDE + kk + t;
                float r0 = fmaxf(fmaf(base[0],               c0.x, c0.y), 0.f);
                float r1 = fmaxf(fmaf(base[8 * ASTRIDE],     c0.x, c0.y), 0.f);
                float r2 = fmaxf(fmaf(base[4],               c1.x, c1.y), 0.f);
                float r3 = fmaxf(fmaf(base[8 * ASTRIDE + 4], c1.x, c1.y), 0.f);
                afrag[im][0] = f2tf32(r0);
                afrag[im][1] = f2tf32(r1);
                afrag[im][2] = f2tf32(r2);
                afrag[im][3] = f2tf32(r3);
            }
#pragma unroll
            for (int jn = 0; jn < 8; jn++) {
                int n = warpN * 64 + jn * 8 + g;
                bfrag[jn][0] = __float_as_uint(pb[(kk + t) * BSTRIDE + n]);
                bfrag[jn][1] = __float_as_uint(pb[(kk + t + 4) * BSTRIDE + n]);
            }
#pragma unroll
            for (int im = 0; im < 2; im++)
#pragma unroll
                for (int jn = 0; jn < 8; jn++) {
                    float4& c = acc[im][jn];
                    asm volatile(
                        "mma.sync.aligned.m16n8k8.row.col.f32.tf32.tf32.f32 "
                        "{%0,%1,%2,%3}, {%4,%5,%6,%7}, {%8,%9}, {%0,%1,%2,%3};"
                        : "+f"(c.x), "+f"(c.y), "+f"(c.z), "+f"(c.w)
                        : "r"(afrag[im][0]), "r"(afrag[im][1]),
                          "r"(afrag[im][2]), "r"(afrag[im][3]),
                          "r"(bfrag[jn][0]), "r"(bfrag[jn][1]));
                }
        }
        __syncthreads();
    }

#pragma unroll
    for (int jn = 0; jn < 8; jn++) {
        int col = bn + warpN * 64 + jn * 8 + 2 * t;
        float bx = bias[col], by = bias[col + 1];
#pragma unroll
        for (int im = 0; im < 2; im++) {
            int row0 = bm + warpM * 32 + im * 16 + g;
            float4 c = acc[im][jn];
            if (row0 < M)
                *(float2*)(C + (long long)row0 * N + col) = make_float2(c.x + bx, c.y + by);
            if (row0 + 8 < M)
                *(float2*)(C + (long long)(row0 + 8) * N + col) = make_float2(c.z + bx, c.w + by);
        }
    }
}

// --- stats -> per-col (scale, shift) ------------------------------------------
__global__ void k_bnprep(const float2* __restrict__ stats,
                         const float* __restrict__ gamma,
                         const float* __restrict__ beta,
                         float2* __restrict__ ss, int D, float invM) {
    int c = blockIdx.x * blockDim.x + threadIdx.x;
    if (c < D) {
        float mu = stats[c].x * invM;
        float var = stats[c].y * invM - mu * mu;
        float sc = gamma[c] * rsqrtf(var + EPS);
        ss[c] = make_float2(sc, beta[c] - mu * sc);
    }
}

// ---------------------------------------------------------------------------

extern "C" void kernel_launch(void* const* d_in, const int* in_sizes, int n_in,
                              void* d_out, int out_size) {
    const float* x      = (const float*)d_in[0];
    const void*  ei     = d_in[1];
    const float* W1     = (const float*)d_in[2];
    const float* b1     = (const float*)d_in[3];
    const float* gamma1 = (const float*)d_in[4];
    const float* beta1  = (const float*)d_in[5];
    const float* W2     = (const float*)d_in[6];
    const float* b2     = (const float*)d_in[7];
    const float* gamma2 = (const float*)d_in[8];
    const float* beta2  = (const float*)d_in[9];
    const float* Wl     = (const float*)d_in[10];
    const float* bl     = (const float*)d_in[11];

    const int H1   = in_sizes[3];               // 256
    const int H2   = in_sizes[7];               // 512
    const int DOUT = in_sizes[11];              // 128
    const int DIN  = in_sizes[2] / H1;          // 128
    const int N    = in_sizes[0] / DIN;         // 50000
    const long long E = in_sizes[1] / 2;        // 500000
    const float invM = 1.0f / (float)N;

    float *dinv, *agg1, *h1, *agg2, *h2, *w1, *w2, *wl;
    float2 *stats1, *stats2, *ss1, *ss2;
    int *cnt, *rowptr, *cursor, *flag, *bsum;
    int2* adj;
    cudaGetSymbolAddress((void**)&dinv,   g_dinv);
    cudaGetSymbolAddress((void**)&cnt,    g_cnt);
    cudaGetSymbolAddress((void**)&rowptr, g_rowptr);
    cudaGetSymbolAddress((void**)&cursor, g_cursor);
    cudaGetSymbolAddress((void**)&bsum,   g_bsum);
    cudaGetSymbolAddress((void**)&adj,    g_adj);
    cudaGetSymbolAddress((void**)&agg1,   g_agg1);
    cudaGetSymbolAddress((void**)&h1,     g_h1);
    cudaGetSymbolAddress((void**)&agg2,   g_agg2);
    cudaGetSymbolAddress((void**)&h2,     g_h2);
    cudaGetSymbolAddress((void**)&w1,     g_w1);
    cudaGetSymbolAddress((void**)&w2,     g_w2);
    cudaGetSymbolAddress((void**)&wl,     g_wl);
    cudaGetSymbolAddress((void**)&stats1, g_stats1);
    cudaGetSymbolAddress((void**)&stats2, g_stats2);
    cudaGetSymbolAddress((void**)&ss1,    g_ss1);
    cudaGetSymbolAddress((void**)&ss2,    g_ss2);
    cudaGetSymbolAddress((void**)&flag,   g_flag32);

    float* out = (float*)d_out;

    cudaFuncSetAttribute(k_gemm_pipe, cudaFuncAttributeMaxDynamicSharedMemorySize, SMEM_PIPE);
    cudaFuncSetAttribute(k_gemm_fin,  cudaFuncAttributeMaxDynamicSharedMemorySize, SMEM_FIN);

    const int scanBlocks = (N + SCAN_BLK - 1) / SCAN_BLK;

    // 1. prep: dtype detect (sampled) + zero, count, scan, fill, weight cvt
    k_detect<<<1, 256>>>((const int*)ei, E, flag);
    k_prep0<<<(N + 255) / 256, 256>>>(cnt, N, stats1, stats2, H1, H2);
    k_count<<<1024, 256>>>(ei, E, flag, cnt);
    k_scan_red<<<scanBlocks, SCAN_BLK>>>(cnt, bsum, N);
    k_scan_top<<<1, 64>>>(bsum, scanBlocks, rowptr, N, (int)E);
    k_scan_apply<<<scanBlocks, SCAN_BLK>>>(cnt, bsum, rowptr, cursor, dinv, N);
    k_fill<<<1024, 256>>>(ei, E, flag, dinv, cursor, adj);
    k_cvtw<<<(H1 * H2 + 255) / 256, 256>>>(W1, W2, Wl, w1, w2, wl,
                                           DIN * H1, H1 * H2, H2 * DOUT);

    const int aggBlocks = (int)(((long long)N * 32 + 255) / 256);

    // 2. layer 1: agg1 = A x (tf32) ; h1 = agg1 @ W1 + b1 (stats fused)
    k_agg<128, false><<<aggBlocks, 256>>>(adj, rowptr, dinv, x, agg1, N, nullptr);
    {
        dim3 grid(H1 / GBN, (N + GBM - 1) / GBM);
        k_gemm_pipe<<<grid, 256, SMEM_PIPE>>>(agg1, w1, b1, h1, stats1, N, H1, DIN);
        k_bnprep<<<(H1 + 255) / 256, 256>>>(stats1, gamma1, beta1, ss1, H1, invM);
    }

    // 3. layer 2: agg2 = A bnrelu(h1) (fused, tf32) ; h2 = agg2 @ W2 + b2
    k_agg<256, true><<<aggBlocks, 256>>>(adj, rowptr, dinv, h1, agg2, N, ss1);
    {
        dim3 grid(H2 / GBN, (N + GBM - 1) / GBM);
        k_gemm_pipe<<<grid, 256, SMEM_PIPE>>>(agg2, w2, b2, h2, stats2, N, H2, H1);
        k_bnprep<<<(H2 + 255) / 256, 256>>>(stats2, gamma2, beta2, ss2, H2, invM);
    }

    // 4. final projection: out = bnrelu(h2) @ Wl + bl (BN fused at frag build)
    {
        dim3 grid(DOUT / GBN, (N + GBM - 1) / GBM);
        k_gemm_fin<<<grid, 256, SMEM_FIN>>>(h2, wl, bl, out, ss2, N, DOUT, H2);
    }
}

// round 6
// speedup vs baseline: 3.3255x; 1.2638x over previous
#include <cuda_runtime.h>
#include <cuda_bf16.h>
#include <cuda_fp16.h>
#include <cstdint>

// ---------------------------------------------------------------------------
// GCN encoder: N=50000, E=500000, 128 -> 256 -> 512 -> 128
// CSR gather aggregation (BN fused, fp16 out) + fp16 tensor-core GEMM pipeline
// ---------------------------------------------------------------------------

#define MAXN 50048
#define MAXE 524288
#define EPS 1e-5f
#define SCAN_BLK 1024

__device__ float  g_dinv[MAXN];
__device__ int    g_cnt[MAXN];
__device__ int    g_rowptr[MAXN + 1];
__device__ int    g_cursor[MAXN];
__device__ int    g_bsum[64];
__device__ int2   g_adj[MAXE];                 // (src, bits(w))
__device__ __half g_agg1h[(size_t)MAXN * 128]; // fp16 agg outputs
__device__ __half g_agg2h[(size_t)MAXN * 256];
__device__ float  g_h1[(size_t)MAXN * 256];    // raw (pre-BN)
__device__ float  g_h2[(size_t)MAXN * 512];
__device__ __half g_w1t[256 * 128];            // fp16 W1^T [N][K]
__device__ __half g_w2t[512 * 256];            // fp16 W2^T
__device__ float  g_wl[512 * 128];             // tf32-rounded Wl
__device__ float2 g_stats1[256];               // (sum, sumsq)
__device__ float2 g_stats2[512];
__device__ float2 g_ss1[256];                  // (scale, shift)
__device__ float2 g_ss2[512];
__device__ int    g_flag32;                    // 1 => edge_index is int32

// ---------------------------------------------------------------------------

__device__ __forceinline__ void red_add_v2(float2* addr, float a, float b) {
    asm volatile("red.global.add.v2.f32 [%0], {%1,%2};"
                 :: "l"(addr), "f"(a), "f"(b) : "memory");
}

__device__ __forceinline__ int load_idx(const void* ei, long long pos, int is32) {
    if (is32) return ((const int*)ei)[pos];
    return (int)(((const long long*)ei)[pos]);
}

__device__ __forceinline__ uint32_t f2tf32(float f) {
    uint32_t u;
    asm("cvt.rna.tf32.f32 %0, %1;" : "=r"(u) : "f"(f));
    return u;
}

__device__ __forceinline__ uint32_t pack_h2(float lo, float hi) {
    uint32_t u;
    asm("cvt.rn.f16x2.f32 %0, %1, %2;" : "=r"(u) : "f"(hi), "f"(lo));
    return u;
}

__device__ __forceinline__ void cp_async16(void* sptr, const void* gptr, int src_bytes) {
    uint32_t sa = (uint32_t)__cvta_generic_to_shared(sptr);
    asm volatile("cp.async.cg.shared.global [%0], [%1], 16, %2;"
                 :: "r"(sa), "l"(gptr), "r"(src_bytes));
}

// --- dtype detect: sample first <=8192 edges; int64 => odd words all zero ---
__global__ void k_detect(const int* __restrict__ ei32, long long E, int* flag) {
    long long lim = E < 8192 ? E : 8192;
    int any = 0;
    for (long long j = threadIdx.x; j < lim; j += blockDim.x)
        if (ei32[2 * j + 1] != 0) any = 1;
    if (any) atomicOr(flag, 1);
}

// --- prep0: zero cnt + stats --------------------------------------------------
__global__ void k_prep0(int* cnt, int n, float2* st1, float2* st2, int d1, int d2) {
    int i = blockIdx.x * blockDim.x + threadIdx.x;
    if (i < n) cnt[i] = 0;
    if (i < d1) st1[i] = make_float2(0.f, 0.f);
    if (i < d2) st2[i] = make_float2(0.f, 0.f);
}

// --- in-degree counts ---------------------------------------------------------
__global__ void k_count(const void* ei, long long E, const int* flag, int* cnt) {
    long long i = blockIdx.x * (long long)blockDim.x + threadIdx.x;
    long long stride = (long long)gridDim.x * blockDim.x;
    int is32 = *flag;
    for (; i < E; i += stride) {
        int d = load_idx(ei, E + i, is32);
        atomicAdd(&cnt[d], 1);
    }
}

// --- 3-pass scan ----------------------------------------------------------------
__global__ __launch_bounds__(SCAN_BLK) void k_scan_red(const int* __restrict__ cnt,
                                                       int* __restrict__ bsum, int n) {
    int i = blockIdx.x * SCAN_BLK + threadIdx.x;
    int v = (i < n) ? cnt[i] : 0;
    int lane = threadIdx.x & 31, wid = threadIdx.x >> 5;
#pragma unroll
    for (int off = 16; off; off >>= 1) v += __shfl_xor_sync(0xffffffffu, v, off);
    __shared__ int ws[32];
    if (lane == 0) ws[wid] = v;
    __syncthreads();
    if (wid == 0) {
        v = ws[lane];
#pragma unroll
        for (int off = 16; off; off >>= 1) v += __shfl_xor_sync(0xffffffffu, v, off);
        if (lane == 0) bsum[blockIdx.x] = v;
    }
}

__global__ void k_scan_top(int* __restrict__ bsum, int nb,
                           int* __restrict__ rowptr, int n, int total) {
    int tid = threadIdx.x, lane = tid & 31, wid = tid >> 5;
    int v = (tid < nb) ? bsum[tid] : 0;
    int x = v;
#pragma unroll
    for (int off = 1; off < 32; off <<= 1) {
        int y = __shfl_up_sync(0xffffffffu, x, off);
        if (lane >= off) x += y;
    }
    __shared__ int ws[2];
    if (lane == 31) ws[wid] = x;
    __syncthreads();
    int excl = x - v + (wid == 1 ? ws[0] : 0);
    if (tid < nb) bsum[tid] = excl;
    if (tid == 0) rowptr[n] = total;
}

__global__ __launch_bounds__(SCAN_BLK) void k_scan_apply(const int* __restrict__ cnt,
                                                         const int* __restrict__ bsum,
                                                         int* __restrict__ rowptr,
                                                         int* __restrict__ cursor,
                                                         float* __restrict__ dinv, int n) {
    int i = blockIdx.x * SCAN_BLK + threadIdx.x;
    int v = (i < n) ? cnt[i] : 0;
    int lane = threadIdx.x & 31, wid = threadIdx.x >> 5;
    int x = v;
#pragma unroll
    for (int off = 1; off < 32; off <<= 1) {
        int y = __shfl_up_sync(0xffffffffu, x, off);
        if (lane >= off) x += y;
    }
    __shared__ int ws[32];
    if (lane == 31) ws[wid] = x;
    __syncthreads();
    if (wid == 0) {
        int w = ws[lane];
#pragma unroll
        for (int off = 1; off < 32; off <<= 1) {
            int y = __shfl_up_sync(0xffffffffu, w, off);
            if (lane >= off) w += y;
        }
        ws[lane] = w;
    }
    __syncthreads();
    int incl = x + (wid > 0 ? ws[wid - 1] : 0);
    int excl = incl - v + bsum[blockIdx.x];
    if (i < n) {
        rowptr[i] = excl;
        cursor[i] = excl;
        dinv[i] = rsqrtf((float)v + 1.0f);
    }
}

// --- bucket-fill adjacency -------------------------------------------------------
__global__ void k_fill(const void* __restrict__ ei, long long E, const int* flag,
                       const float* __restrict__ dinv, int* __restrict__ cursor,
                       int2* __restrict__ adj) {
    long long i = blockIdx.x * (long long)blockDim.x + threadIdx.x;
    long long stride = (long long)gridDim.x * blockDim.x;
    int is32 = *flag;
    for (; i < E; i += stride) {
        int s = load_idx(ei, i, is32);
        int d = load_idx(ei, E + i, is32);
        float w = dinv[s] * dinv[d];
        int pos = atomicAdd(&cursor[d], 1);
        adj[pos] = make_int2(s, __float_as_int(w));
    }
}

// --- weight convert: W1,W2 -> fp16 transposed [N][K]; Wl -> tf32 -----------------
__global__ void k_cvtw(const float* __restrict__ W1, const float* __restrict__ W2,
                       const float* __restrict__ W3,
                       __half* __restrict__ t1, __half* __restrict__ t2,
                       float* __restrict__ o3,
                       int K1, int N1, int K2, int N2, int n3) {
    int i = blockIdx.x * blockDim.x + threadIdx.x;
    if (i < K1 * N1) {
        int k = i / N1, n = i % N1;
        t1[n * K1 + k] = __float2half_rn(W1[i]);
    }
    if (i < K2 * N2) {
        int k = i / N2, n = i % N2;
        t2[n * K2 + k] = __float2half_rn(W2[i]);
    }
    if (i < n3) o3[i] = __uint_as_float(f2tf32(W3[i]));
}

// --- CSR aggregation, optional fused BN+ReLU on input, fp16 output ---------------
template<int D, bool BN>
__global__ __launch_bounds__(256) void k_agg(const int2* __restrict__ adj,
                                             const int* __restrict__ rowptr,
                                             const float* __restrict__ dinv,
                                             const float* __restrict__ X,
                                             __half* __restrict__ out, int N,
                                             const float2* __restrict__ ss) {
    int node = (blockIdx.x * blockDim.x + threadIdx.x) >> 5;
    int lane = threadIdx.x & 31;
    if (node >= N) return;
    constexpr int V = D / 128;
    float2 sr[V * 4];
    if (BN) {
#pragma unroll
        for (int v = 0; v < V; v++)
#pragma unroll
            for (int j = 0; j < 4; j++)
                sr[v * 4 + j] = ss[v * 128 + lane * 4 + j];
    }
    auto xf = [&](float4 a, int v) -> float4 {
        if (BN) {
            a.x = fmaxf(fmaf(a.x, sr[v*4+0].x, sr[v*4+0].y), 0.f);
            a.y = fmaxf(fmaf(a.y, sr[v*4+1].x, sr[v*4+1].y), 0.f);
            a.z = fmaxf(fmaf(a.z, sr[v*4+2].x, sr[v*4+2].y), 0.f);
            a.w = fmaxf(fmaf(a.w, sr[v*4+3].x, sr[v*4+3].y), 0.f);
        }
        return a;
    };
    float w0 = dinv[node]; w0 *= w0;
    const float4* xs = (const float4*)(X + (size_t)node * D);
    float4 acc[V];
#pragma unroll
    for (int v = 0; v < V; v++) {
        float4 a = xf(xs[v * 32 + lane], v);
        acc[v] = make_float4(a.x * w0, a.y * w0, a.z * w0, a.w * w0);
    }
    int j = rowptr[node], end = rowptr[node + 1];
    int2 e = (j < end) ? adj[j] : make_int2(0, 0);
    for (; j < end; j++) {
        int2 cur = e;
        if (j + 1 < end) e = adj[j + 1];
        float w = __int_as_float(cur.y);
        const float4* s = (const float4*)(X + (size_t)cur.x * D);
#pragma unroll
        for (int v = 0; v < V; v++) {
            float4 a = xf(s[v * 32 + lane], v);
            acc[v].x += w * a.x; acc[v].y += w * a.y;
            acc[v].z += w * a.z; acc[v].w += w * a.w;
        }
    }
    uint2* o = (uint2*)(out + (size_t)node * D);
#pragma unroll
    for (int v = 0; v < V; v++) {
        float4 a = acc[v];
        o[v * 32 + lane] = make_uint2(pack_h2(a.x, a.y), pack_h2(a.z, a.w));
    }
}

// ---------------------------------------------------------------------------
// fp16 pipelined GEMM: C[M,N] = A[M,K] @ Wt[N,K]^T + bias (fp32 accum).
// A fp16 [M][K], Wt fp16 [N][K]. Block 128x128, 8 warps, BK=32, cp.async x2.
// Fused bias + BN stats epilogue.
// ---------------------------------------------------------------------------
#define GBM 128
#define GBN 128
#define HASTR 40                        // halves per smem row (32 + 8 pad)
#define HTSZ (128 * HASTR)              // halves per tile stage
#define SMEM_H ((4 * HTSZ) * 2)         // 2 stages A + 2 stages B, bytes

__global__ __launch_bounds__(256) void k_gemm_h(const __half* __restrict__ A,
                                                const __half* __restrict__ Bt,
                                                const float* __restrict__ bias,
                                                float* __restrict__ C,
                                                float2* __restrict__ stats,
                                                int M, int N, int K) {
    extern __shared__ __half smh[];
    __half* As = smh;                   // 2 stages
    __half* Bs = smh + 2 * HTSZ;        // 2 stages

    const int tid  = threadIdx.x;
    const int lane = tid & 31;
    const int warpId = tid >> 5;
    const int warpM = warpId & 3;
    const int warpN = warpId >> 2;
    const int g = lane >> 2;
    const int t = lane & 3;
    const int bm = blockIdx.y * GBM;
    const int bn = blockIdx.x * GBN;

    const int l_row = tid >> 2;         // 0..63
    const int l_chk = (tid & 3) * 8;    // half offset of 16B chunk

    float4 acc[2][8];
#pragma unroll
    for (int i = 0; i < 2; i++)
#pragma unroll
        for (int j = 0; j < 8; j++)
            acc[i][j] = make_float4(0.f, 0.f, 0.f, 0.f);

    auto load_stage = [&](int stg, int k0) {
        __half* pa = As + stg * HTSZ;
        __half* pb = Bs + stg * HTSZ;
#pragma unroll
        for (int i = 0; i < 2; i++) {
            int row = i * 64 + l_row;
            int gm = bm + row;
            int ok = (gm < M) ? 16 : 0;
            int gmc = min(gm, M - 1);
            cp_async16(pa + row * HASTR + l_chk, A + (size_t)gmc * K + k0 + l_chk, ok);
        }
#pragma unroll
        for (int i = 0; i < 2; i++) {
            int row = i * 64 + l_row;
            cp_async16(pb + row * HASTR + l_chk, Bt + (size_t)(bn + row) * K + k0 + l_chk, 16);
        }
    };

    const int nk = K / 32;
    load_stage(0, 0);
    asm volatile("cp.async.commit_group;");

    for (int tk = 0; tk < nk; tk++) {
        if (tk + 1 < nk) {
            load_stage((tk + 1) & 1, (tk + 1) * 32);
            asm volatile("cp.async.commit_group;");
            asm volatile("cp.async.wait_group 1;");
        } else {
            asm volatile("cp.async.wait_group 0;");
        }
        __syncthreads();

        const __half* pa = As + (tk & 1) * HTSZ;
        const __half* pb = Bs + (tk & 1) * HTSZ;
#pragma unroll
        for (int kk = 0; kk < 32; kk += 16) {
            uint32_t afrag[2][4];
            uint32_t bfrag[8][2];
#pragma unroll
            for (int im = 0; im < 2; im++) {
                const __half* base = pa + (warpM * 32 + im * 16 + g) * HASTR + kk + 2 * t;
                afrag[im][0] = *(const uint32_t*)(base);
                afrag[im][1] = *(const uint32_t*)(base + 8 * HASTR);
                afrag[im][2] = *(const uint32_t*)(base + 8);
                afrag[im][3] = *(const uint32_t*)(base + 8 * HASTR + 8);
            }
#pragma unroll
            for (int jn = 0; jn < 8; jn++) {
                const __half* base = pb + (warpN * 64 + jn * 8 + g) * HASTR + kk + 2 * t;
                bfrag[jn][0] = *(const uint32_t*)(base);
                bfrag[jn][1] = *(const uint32_t*)(base + 8);
            }
#pragma unroll
            for (int im = 0; im < 2; im++)
#pragma unroll
                for (int jn = 0; jn < 8; jn++) {
                    float4& c = acc[im][jn];
                    asm volatile(
                        "mma.sync.aligned.m16n8k16.row.col.f32.f16.f16.f32 "
                        "{%0,%1,%2,%3}, {%4,%5,%6,%7}, {%8,%9}, {%0,%1,%2,%3};"
                        : "+f"(c.x), "+f"(c.y), "+f"(c.z), "+f"(c.w)
                        : "r"(afrag[im][0]), "r"(afrag[im][1]),
                          "r"(afrag[im][2]), "r"(afrag[im][3]),
                          "r"(bfrag[jn][0]), "r"(bfrag[jn][1]));
                }
        }
        __syncthreads();
    }

#pragma unroll
    for (int jn = 0; jn < 8; jn++) {
        int col = bn + warpN * 64 + jn * 8 + 2 * t;
        float bx = bias[col], by = bias[col + 1];
        float s0 = 0.f, q0 = 0.f, s1 = 0.f, q1 = 0.f;
#pragma unroll
        for (int im = 0; im < 2; im++) {
            int row0 = bm + warpM * 32 + im * 16 + g;
            float4 c = acc[im][jn];
            if (row0 < M) {
                float ox = c.x + bx, oy = c.y + by;
                *(float2*)(C + (long long)row0 * N + col) = make_float2(ox, oy);
                s0 += ox; q0 += ox * ox; s1 += oy; q1 += oy * oy;
            }
            if (row0 + 8 < M) {
                float oz = c.z + bx, ow = c.w + by;
                *(float2*)(C + (long long)(row0 + 8) * N + col) = make_float2(oz, ow);
                s0 += oz; q0 += oz * oz; s1 += ow; q1 += ow * ow;
            }
        }
#pragma unroll
        for (int m = 4; m < 32; m <<= 1) {
            s0 += __shfl_xor_sync(0xffffffffu, s0, m);
            q0 += __shfl_xor_sync(0xffffffffu, q0, m);
            s1 += __shfl_xor_sync(0xffffffffu, s1, m);
            q1 += __shfl_xor_sync(0xffffffffu, q1, m);
        }
        if (g == 0) {
            red_add_v2(&stats[col], s0, q0);
            red_add_v2(&stats[col + 1], s1, q1);
        }
    }
}

// ---------------------------------------------------------------------------
// Final GEMM (tf32, pipelined): A = raw h2 (BN2+ReLU+cvt at frag build),
// B = pre-converted tf32 Wl.
// ---------------------------------------------------------------------------
#define GBK 32
#define ASTRIDE 36
#define BSTRIDE 132
#define ASZ (GBM * ASTRIDE)
#define BSZ (GBK * BSTRIDE)
#define SMEM_FIN ((2 * ASZ + 2 * BSZ) * 4 + 512 * 8)

__global__ __launch_bounds__(256) void k_gemm_fin(const float* __restrict__ A,
                                                  const float* __restrict__ Bw,
                                                  const float* __restrict__ bias,
                                                  float* __restrict__ C,
                                                  const float2* __restrict__ ssA,
                                                  int M, int N, int K) {
    extern __shared__ float sm[];
    float* As = sm;
    float* Bs = sm + 2 * ASZ;
    float2* ssm = (float2*)(sm + 2 * ASZ + 2 * BSZ);

    const int tid  = threadIdx.x;
    const int lane = tid & 31;
    const int warpId = tid >> 5;
    const int warpM = warpId & 3;
    const int warpN = warpId >> 2;
    const int g = lane >> 2;
    const int t = lane & 3;
    const int bm = blockIdx.y * GBM;
    const int bn = blockIdx.x * GBN;

    for (int c = tid; c < K; c += 256) ssm[c] = ssA[c];

    const int a_row = tid >> 3;
    const int a_col = (tid & 7) * 4;
    const int b_k  = tid >> 5;
    const int b_n4 = (tid & 31) * 4;

    float4 acc[2][8];
#pragma unroll
    for (int i = 0; i < 2; i++)
#pragma unroll
        for (int j = 0; j < 8; j++)
            acc[i][j] = make_float4(0.f, 0.f, 0.f, 0.f);

    auto load_stage = [&](int stg, int k0) {
        float* pa = As + stg * ASZ;
        float* pb = Bs + stg * BSZ;
#pragma unroll
        for (int i = 0; i < 4; i++) {
            int row = i * 32 + a_row;
            int gm = bm + row;
            int ok = (gm < M) ? 16 : 0;
            int gmc = min(gm, M - 1);
            cp_async16(pa + row * ASTRIDE + a_col, A + (long long)gmc * K + k0 + a_col, ok);
        }
#pragma unroll
        for (int i = 0; i < 4; i++) {
            int kk = i * 8 + b_k;
            cp_async16(pb + kk * BSTRIDE + b_n4, Bw + (long long)(k0 + kk) * N + bn + b_n4, 16);
        }
    };

    const int nk = K / GBK;
    load_stage(0, 0);
    asm volatile("cp.async.commit_group;");

    for (int tk = 0; tk < nk; tk++) {
        if (tk + 1 < nk) {
            load_stage((tk + 1) & 1, (tk + 1) * GBK);
            asm volatile("cp.async.commit_group;");
            asm volatile("cp.async.wait_group 1;");
        } else {
            asm volatile("cp.async.wait_group 0;");
        }
        __syncthreads();

        const float* pa = As + (tk & 1) * ASZ;
        const float* pb = Bs + (tk & 1) * BSZ;
        const int kbase = tk * GBK;
#pragma unroll
        for (int kk = 0; kk < GBK; kk += 8) {
            float2 c0 = ssm[kbase + kk + t];
            float2 c1 = ssm[kbase + kk + t + 4];
            uint32_t afrag[2][4];
            uint32_t bfrag[8][2];
#pragma unroll
            for (int im = 0; im < 2; im++) {
                const float* base = pa + (warpM * 32 + im * 16 + g) * ASTRIDE + kk + t;
                float r0 = fmaxf(fmaf(base[0],               c0.x, c0.y), 0.f);
                float r1 = fmaxf(fmaf(base[8 * ASTRIDE],     c0.x, c0.y), 0.f);
                float r2 = fmaxf(fmaf(base[4],               c1.x, c1.y), 0.f);
                float r3 = fmaxf(fmaf(base[8 * ASTRIDE + 4], c1.x, c1.y), 0.f);
                afrag[im][0] = f2tf32(r0);
                afrag[im][1] = f2tf32(r1);
                afrag[im][2] = f2tf32(r2);
                afrag[im][3] = f2tf32(r3);
            }
#pragma unroll
            for (int jn = 0; jn < 8; jn++) {
                int n = warpN * 64 + jn * 8 + g;
                bfrag[jn][0] = __float_as_uint(pb[(kk + t) * BSTRIDE + n]);
                bfrag[jn][1] = __float_as_uint(pb[(kk + t + 4) * BSTRIDE + n]);
            }
#pragma unroll
            for (int im = 0; im < 2; im++)
#pragma unroll
                for (int jn = 0; jn < 8; jn++) {
                    float4& c = acc[im][jn];
                    asm volatile(
                        "mma.sync.aligned.m16n8k8.row.col.f32.tf32.tf32.f32 "
                        "{%0,%1,%2,%3}, {%4,%5,%6,%7}, {%8,%9}, {%0,%1,%2,%3};"
                        : "+f"(c.x), "+f"(c.y), "+f"(c.z), "+f"(c.w)
                        : "r"(afrag[im][0]), "r"(afrag[im][1]),
                          "r"(afrag[im][2]), "r"(afrag[im][3]),
                          "r"(bfrag[jn][0]), "r"(bfrag[jn][1]));
                }
        }
        __syncthreads();
    }

#pragma unroll
    for (int jn = 0; jn < 8; jn++) {
        int col = bn + warpN * 64 + jn * 8 + 2 * t;
        float bx = bias[col], by = bias[col + 1];
#pragma unroll
        for (int im = 0; im < 2; im++) {
            int row0 = bm + warpM * 32 + im * 16 + g;
            float4 c = acc[im][jn];
            if (row0 < M)
                *(float2*)(C + (long long)row0 * N + col) = make_float2(c.x + bx, c.y + by);
            if (row0 + 8 < M)
                *(float2*)(C + (long long)(row0 + 8) * N + col) = make_float2(c.z + bx, c.w + by);
        }
    }
}

// --- stats -> per-col (scale, shift) ------------------------------------------
__global__ void k_bnprep(const float2* __restrict__ stats,
                         const float* __restrict__ gamma,
                         const float* __restrict__ beta,
                         float2* __restrict__ ss, int D, float invM) {
    int c = blockIdx.x * blockDim.x + threadIdx.x;
    if (c < D) {
        float mu = stats[c].x * invM;
        float var = stats[c].y * invM - mu * mu;
        float sc = gamma[c] * rsqrtf(var + EPS);
        ss[c] = make_float2(sc, beta[c] - mu * sc);
    }
}

// ---------------------------------------------------------------------------

extern "C" void kernel_launch(void* const* d_in, const int* in_sizes, int n_in,
                              void* d_out, int out_size) {
    const float* x      = (const float*)d_in[0];
    const void*  ei     = d_in[1];
    const float* W1     = (const float*)d_in[2];
    const float* b1     = (const float*)d_in[3];
    const float* gamma1 = (const float*)d_in[4];
    const float* beta1  = (const float*)d_in[5];
    const float* W2     = (const float*)d_in[6];
    const float* b2     = (const float*)d_in[7];
    const float* gamma2 = (const float*)d_in[8];
    const float* beta2  = (const float*)d_in[9];
    const float* Wl     = (const float*)d_in[10];
    const float* bl     = (const float*)d_in[11];

    const int H1   = in_sizes[3];               // 256
    const int H2   = in_sizes[7];               // 512
    const int DOUT = in_sizes[11];              // 128
    const int DIN  = in_sizes[2] / H1;          // 128
    const int N    = in_sizes[0] / DIN;         // 50000
    const long long E = in_sizes[1] / 2;        // 500000
    const float invM = 1.0f / (float)N;

    float *dinv, *h1, *h2, *wl;
    __half *agg1h, *agg2h, *w1t, *w2t;
    float2 *stats1, *stats2, *ss1, *ss2;
    int *cnt, *rowptr, *cursor, *flag, *bsum;
    int2* adj;
    cudaGetSymbolAddress((void**)&dinv,   g_dinv);
    cudaGetSymbolAddress((void**)&cnt,    g_cnt);
    cudaGetSymbolAddress((void**)&rowptr, g_rowptr);
    cudaGetSymbolAddress((void**)&cursor, g_cursor);
    cudaGetSymbolAddress((void**)&bsum,   g_bsum);
    cudaGetSymbolAddress((void**)&adj,    g_adj);
    cudaGetSymbolAddress((void**)&agg1h,  g_agg1h);
    cudaGetSymbolAddress((void**)&agg2h,  g_agg2h);
    cudaGetSymbolAddress((void**)&h1,     g_h1);
    cudaGetSymbolAddress((void**)&h2,     g_h2);
    cudaGetSymbolAddress((void**)&w1t,    g_w1t);
    cudaGetSymbolAddress((void**)&w2t,    g_w2t);
    cudaGetSymbolAddress((void**)&wl,     g_wl);
    cudaGetSymbolAddress((void**)&stats1, g_stats1);
    cudaGetSymbolAddress((void**)&stats2, g_stats2);
    cudaGetSymbolAddress((void**)&ss1,    g_ss1);
    cudaGetSymbolAddress((void**)&ss2,    g_ss2);
    cudaGetSymbolAddress((void**)&flag,   g_flag32);

    float* out = (float*)d_out;

    cudaFuncSetAttribute(k_gemm_h,   cudaFuncAttributeMaxDynamicSharedMemorySize, SMEM_H);
    cudaFuncSetAttribute(k_gemm_fin, cudaFuncAttributeMaxDynamicSharedMemorySize, SMEM_FIN);

    const int scanBlocks = (N + SCAN_BLK - 1) / SCAN_BLK;

    // 1. prep
    k_detect<<<1, 256>>>((const int*)ei, E, flag);
    k_prep0<<<(N + 255) / 256, 256>>>(cnt, N, stats1, stats2, H1, H2);
    k_count<<<1024, 256>>>(ei, E, flag, cnt);
    k_scan_red<<<scanBlocks, SCAN_BLK>>>(cnt, bsum, N);
    k_scan_top<<<1, 64>>>(bsum, scanBlocks, rowptr, N, (int)E);
    k_scan_apply<<<scanBlocks, SCAN_BLK>>>(cnt, bsum, rowptr, cursor, dinv, N);
    k_fill<<<1024, 256>>>(ei, E, flag, dinv, cursor, adj);
    k_cvtw<<<(H1 * H2 + 255) / 256, 256>>>(W1, W2, Wl, w1t, w2t, wl,
                                           DIN, H1, H1, H2, H2 * DOUT);

    const int aggBlocks = (int)(((long long)N * 32 + 255) / 256);

    // 2. layer 1: agg1 = A x (fp16) ; h1 = agg1 @ W1 + b1 (stats fused)
    k_agg<128, false><<<aggBlocks, 256>>>(adj, rowptr, dinv, x, agg1h, N, nullptr);
    {
        dim3 grid(H1 / GBN, (N + GBM - 1) / GBM);
        k_gemm_h<<<grid, 256, SMEM_H>>>(agg1h, w1t, b1, h1, stats1, N, H1, DIN);
        k_bnprep<<<(H1 + 255) / 256, 256>>>(stats1, gamma1, beta1, ss1, H1, invM);
    }

    // 3. layer 2: agg2 = A bnrelu(h1) (fused, fp16) ; h2 = agg2 @ W2 + b2
    k_agg<256, true><<<aggBlocks, 256>>>(adj, rowptr, dinv, h1, agg2h, N, ss1);
    {
        dim3 grid(H2 / GBN, (N + GBM - 1) / GBM);
        k_gemm_h<<<grid, 256, SMEM_H>>>(agg2h, w2t, b2, h2, stats2, N, H2, H1);
        k_bnprep<<<(H2 + 255) / 256, 256>>>(stats2, gamma2, beta2, ss2, H2, invM);
    }

    // 4. final projection: out = bnrelu(h2) @ Wl + bl (BN fused at frag build)
    {
        dim3 grid(DOUT / GBN, (N + GBM - 1) / GBM);
        k_gemm_fin<<<grid, 256, SMEM_FIN>>>(h2, wl, bl, out, ss2, N, DOUT, H2);
    }
}

// round 7
// speedup vs baseline: 3.5471x; 1.0666x over previous
#include <cuda_runtime.h>
#include <cuda_bf16.h>
#include <cuda_fp16.h>
#include <cstdint>

// ---------------------------------------------------------------------------
// GCN encoder: N=50000, E=500000, 128 -> 256 -> 512 -> 128
// CSR gather aggregation (BN fused, fp16 activations end-to-end)
// + fp16 tensor-core GEMM pipelines with fused BN stats
// ---------------------------------------------------------------------------

#define MAXN 50048
#define MAXE 524288
#define EPS 1e-5f
#define SCAN_BLK 1024

__device__ float  g_dinv[MAXN];
__device__ int    g_cnt[MAXN];
__device__ int    g_rowptr[MAXN + 1];
__device__ int    g_cursor[MAXN];
__device__ int    g_bsum[64];
__device__ int2   g_adj[MAXE];                 // (src, bits(w))
__device__ __half g_agg1h[(size_t)MAXN * 128]; // fp16 agg outputs
__device__ __half g_agg2h[(size_t)MAXN * 256];
__device__ __half g_h1[(size_t)MAXN * 256];    // fp16 raw (pre-BN)
__device__ __half g_h2[(size_t)MAXN * 512];
__device__ __half g_w1t[256 * 128];            // fp16 W1^T [N][K]
__device__ __half g_w2t[512 * 256];            // fp16 W2^T
__device__ __half g_wlt[128 * 512];            // fp16 Wl^T
__device__ float2 g_stats1[256];               // (sum, sumsq)
__device__ float2 g_stats2[512];
__device__ float2 g_ss1[256];                  // (scale, shift)
__device__ float2 g_ss2[512];
__device__ int    g_flag32;                    // 1 => edge_index is int32

// ---------------------------------------------------------------------------

__device__ __forceinline__ void red_add_v2(float2* addr, float a, float b) {
    asm volatile("red.global.add.v2.f32 [%0], {%1,%2};"
                 :: "l"(addr), "f"(a), "f"(b) : "memory");
}

__device__ __forceinline__ int load_idx(const void* ei, long long pos, int is32) {
    if (is32) return ((const int*)ei)[pos];
    return (int)(((const long long*)ei)[pos]);
}

__device__ __forceinline__ uint32_t pack_h2(float lo, float hi) {
    uint32_t u;
    asm("cvt.rn.f16x2.f32 %0, %1, %2;" : "=r"(u) : "f"(hi), "f"(lo));
    return u;
}

__device__ __forceinline__ float2 unpack_h2(uint32_t u) {
    __half2 h = *(__half2*)&u;
    return __half22float2(h);
}

__device__ __forceinline__ void cp_async16(void* sptr, const void* gptr, int src_bytes) {
    uint32_t sa = (uint32_t)__cvta_generic_to_shared(sptr);
    asm volatile("cp.async.cg.shared.global [%0], [%1], 16, %2;"
                 :: "r"(sa), "l"(gptr), "r"(src_bytes));
}

// --- prep0 (+fused dtype detect on block 0): zero cnt + stats ----------------
__global__ void k_prep0(const int* __restrict__ ei32, long long E,
                        int* cnt, int n, float2* st1, float2* st2,
                        int d1, int d2, int* flag) {
    int i = blockIdx.x * blockDim.x + threadIdx.x;
    if (blockIdx.x == 0) {
        long long lim = E < 8192 ? E : 8192;
        int any = 0;
        for (long long j = threadIdx.x; j < lim; j += blockDim.x)
            if (ei32[2 * j + 1] != 0) any = 1;
        if (any) atomicOr(flag, 1);
    }
    if (i < n) cnt[i] = 0;
    if (i < d1) st1[i] = make_float2(0.f, 0.f);
    if (i < d2) st2[i] = make_float2(0.f, 0.f);
}

// --- in-degree counts ---------------------------------------------------------
__global__ void k_count(const void* ei, long long E, const int* flag, int* cnt) {
    long long i = blockIdx.x * (long long)blockDim.x + threadIdx.x;
    long long stride = (long long)gridDim.x * blockDim.x;
    int is32 = *flag;
    for (; i < E; i += stride) {
        int d = load_idx(ei, E + i, is32);
        atomicAdd(&cnt[d], 1);
    }
}

// --- scan pass 1: per-block sums -----------------------------------------------
__global__ __launch_bounds__(SCAN_BLK) void k_scan_red(const int* __restrict__ cnt,
                                                       int* __restrict__ bsum, int n) {
    int i = blockIdx.x * SCAN_BLK + threadIdx.x;
    int v = (i < n) ? cnt[i] : 0;
    int lane = threadIdx.x & 31, wid = threadIdx.x >> 5;
#pragma unroll
    for (int off = 16; off; off >>= 1) v += __shfl_xor_sync(0xffffffffu, v, off);
    __shared__ int ws[32];
    if (lane == 0) ws[wid] = v;
    __syncthreads();
    if (wid == 0) {
        v = ws[lane];
#pragma unroll
        for (int off = 16; off; off >>= 1) v += __shfl_xor_sync(0xffffffffu, v, off);
        if (lane == 0) bsum[blockIdx.x] = v;
    }
}

// --- scan pass 2: per-block offset (reduce bsum[<blk]) + local scan + apply ----
__global__ __launch_bounds__(SCAN_BLK) void k_scan_apply(const int* __restrict__ cnt,
                                                         const int* __restrict__ bsum, int nb,
                                                         int* __restrict__ rowptr,
                                                         int* __restrict__ cursor,
                                                         float* __restrict__ dinv, int n) {
    int tid = threadIdx.x;
    int lane = tid & 31, wid = tid >> 5;
    __shared__ int ws[32];
    __shared__ int s_off;

    // block offset = sum of bsum[0 .. blockIdx.x)
    int b = (tid < nb && tid < blockIdx.x) ? bsum[tid] : 0;
#pragma unroll
    for (int off = 16; off; off >>= 1) b += __shfl_xor_sync(0xffffffffu, b, off);
    if (lane == 0) ws[wid] = b;
    __syncthreads();
    if (wid == 0) {
        int w = ws[lane];
#pragma unroll
        for (int off = 16; off; off >>= 1) w += __shfl_xor_sync(0xffffffffu, w, off);
        if (lane == 0) s_off = w;
    }
    __syncthreads();
    int offset = s_off;
    __syncthreads();   // ws reuse barrier

    int i = blockIdx.x * SCAN_BLK + tid;
    int v = (i < n) ? cnt[i] : 0;
    int x = v;
#pragma unroll
    for (int off = 1; off < 32; off <<= 1) {
        int y = __shfl_up_sync(0xffffffffu, x, off);
        if (lane >= off) x += y;
    }
    if (lane == 31) ws[wid] = x;
    __syncthreads();
    if (wid == 0) {
        int w = ws[lane];
#pragma unroll
        for (int off = 1; off < 32; off <<= 1) {
            int y = __shfl_up_sync(0xffffffffu, w, off);
            if (lane >= off) w += y;
        }
        ws[lane] = w;
    }
    __syncthreads();
    int incl = x + (wid > 0 ? ws[wid - 1] : 0);
    int excl = incl - v + offset;
    if (i < n) {
        rowptr[i] = excl;
        cursor[i] = excl;
        dinv[i] = rsqrtf((float)v + 1.0f);
        if (i == n - 1) rowptr[n] = excl + v;
    }
}

// --- bucket-fill adjacency -------------------------------------------------------
__global__ void k_fill(const void* __restrict__ ei, long long E, const int* flag,
                       const float* __restrict__ dinv, int* __restrict__ cursor,
                       int2* __restrict__ adj) {
    long long i = blockIdx.x * (long long)blockDim.x + threadIdx.x;
    long long stride = (long long)gridDim.x * blockDim.x;
    int is32 = *flag;
    for (; i < E; i += stride) {
        int s = load_idx(ei, i, is32);
        int d = load_idx(ei, E + i, is32);
        float w = dinv[s] * dinv[d];
        int pos = atomicAdd(&cursor[d], 1);
        adj[pos] = make_int2(s, __float_as_int(w));
    }
}

// --- weight convert: all three -> fp16 transposed [N][K] --------------------------
__global__ void k_cvtw(const float* __restrict__ W1, const float* __restrict__ W2,
                       const float* __restrict__ W3,
                       __half* __restrict__ t1, __half* __restrict__ t2,
                       __half* __restrict__ t3,
                       int K1, int N1, int K2, int N2, int K3, int N3) {
    int i = blockIdx.x * blockDim.x + threadIdx.x;
    if (i < K1 * N1) {
        int k = i / N1, n = i % N1;
        t1[n * K1 + k] = __float2half_rn(W1[i]);
    }
    if (i < K2 * N2) {
        int k = i / N2, n = i % N2;
        t2[n * K2 + k] = __float2half_rn(W2[i]);
    }
    if (i < K3 * N3) {
        int k = i / N3, n = i % N3;
        t3[n * K3 + k] = __float2half_rn(W3[i]);
    }
}

// --- agg layer 1: fp32 x in, fp16 out (no BN) -------------------------------------
__global__ __launch_bounds__(256) void k_agg1(const int2* __restrict__ adj,
                                              const int* __restrict__ rowptr,
                                              const float* __restrict__ dinv,
                                              const float* __restrict__ X,
                                              __half* __restrict__ out, int N) {
    int node = (blockIdx.x * blockDim.x + threadIdx.x) >> 5;
    int lane = threadIdx.x & 31;
    if (node >= N) return;
    float w0 = dinv[node]; w0 *= w0;
    float4 a = ((const float4*)(X + (size_t)node * 128))[lane];
    float4 acc = make_float4(a.x * w0, a.y * w0, a.z * w0, a.w * w0);
    int j = rowptr[node], end = rowptr[node + 1];
    int2 e = (j < end) ? adj[j] : make_int2(0, 0);
    for (; j < end; j++) {
        int2 cur = e;
        if (j + 1 < end) e = adj[j + 1];
        float w = __int_as_float(cur.y);
        float4 s = ((const float4*)(X + (size_t)cur.x * 128))[lane];
        acc.x += w * s.x; acc.y += w * s.y;
        acc.z += w * s.z; acc.w += w * s.w;
    }
    ((uint2*)(out + (size_t)node * 128))[lane] =
        make_uint2(pack_h2(acc.x, acc.y), pack_h2(acc.z, acc.w));
}

// --- agg layer 2: fp16 h1 in (BN+ReLU fused), fp16 out, D=256 ---------------------
__global__ __launch_bounds__(256) void k_agg2(const int2* __restrict__ adj,
                                              const int* __restrict__ rowptr,
                                              const float* __restrict__ dinv,
                                              const __half* __restrict__ X,
                                              __half* __restrict__ out, int N,
                                              const float2* __restrict__ ss) {
    int node = (blockIdx.x * blockDim.x + threadIdx.x) >> 5;
    int lane = threadIdx.x & 31;
    if (node >= N) return;
    float2 sr[8];
#pragma unroll
    for (int j = 0; j < 8; j++) sr[j] = ss[lane * 8 + j];

    float acc[8];
    float w0 = dinv[node]; w0 *= w0;
    {
        uint4 u = ((const uint4*)(X + (size_t)node * 256))[lane];
        float2 f0 = unpack_h2(u.x), f1 = unpack_h2(u.y);
        float2 f2 = unpack_h2(u.z), f3 = unpack_h2(u.w);
        float f[8] = {f0.x, f0.y, f1.x, f1.y, f2.x, f2.y, f3.x, f3.y};
#pragma unroll
        for (int j = 0; j < 8; j++)
            acc[j] = w0 * fmaxf(fmaf(f[j], sr[j].x, sr[j].y), 0.f);
    }
    int j = rowptr[node], end = rowptr[node + 1];
    int2 e = (j < end) ? adj[j] : make_int2(0, 0);
    for (; j < end; j++) {
        int2 cur = e;
        if (j + 1 < end) e = adj[j + 1];
        float w = __int_as_float(cur.y);
        uint4 u = ((const uint4*)(X + (size_t)cur.x * 256))[lane];
        float2 f0 = unpack_h2(u.x), f1 = unpack_h2(u.y);
        float2 f2 = unpack_h2(u.z), f3 = unpack_h2(u.w);
        float f[8] = {f0.x, f0.y, f1.x, f1.y, f2.x, f2.y, f3.x, f3.y};
#pragma unroll
        for (int jj = 0; jj < 8; jj++)
            acc[jj] += w * fmaxf(fmaf(f[jj], sr[jj].x, sr[jj].y), 0.f);
    }
    uint4 o;
    o.x = pack_h2(acc[0], acc[1]);
    o.y = pack_h2(acc[2], acc[3]);
    o.z = pack_h2(acc[4], acc[5]);
    o.w = pack_h2(acc[6], acc[7]);
    ((uint4*)(out + (size_t)node * 256))[lane] = o;
}

// ---------------------------------------------------------------------------
// fp16 pipelined GEMM: C[M,N] = A[M,K] @ Wt[N,K]^T + bias (fp32 accum),
// C stored fp16 (raw pre-BN), fused per-column BN stats (fp32, pre-rounding).
// Block 128x128, 8 warps, BK=32, cp.async 2-stage.
// ---------------------------------------------------------------------------
#define GBM 128
#define GBN 128
#define HASTR 40                        // halves per smem row (32 + 8 pad)
#define HTSZ (128 * HASTR)              // halves per tile stage
#define SMEM_H ((4 * HTSZ) * 2)         // bytes
#define SMEM_FINH (SMEM_H + 512 * 8)

__global__ __launch_bounds__(256) void k_gemm_h(const __half* __restrict__ A,
                                                const __half* __restrict__ Bt,
                                                const float* __restrict__ bias,
                                                __half* __restrict__ C,
                                                float2* __restrict__ stats,
                                                int M, int N, int K) {
    extern __shared__ __half smh[];
    __half* As = smh;
    __half* Bs = smh + 2 * HTSZ;

    const int tid  = threadIdx.x;
    const int lane = tid & 31;
    const int warpId = tid >> 5;
    const int warpM = warpId & 3;
    const int warpN = warpId >> 2;
    const int g = lane >> 2;
    const int t = lane & 3;
    const int bm = blockIdx.y * GBM;
    const int bn = blockIdx.x * GBN;

    const int l_row = tid >> 2;
    const int l_chk = (tid & 3) * 8;

    float4 acc[2][8];
#pragma unroll
    for (int i = 0; i < 2; i++)
#pragma unroll
        for (int j = 0; j < 8; j++)
            acc[i][j] = make_float4(0.f, 0.f, 0.f, 0.f);

    auto load_stage = [&](int stg, int k0) {
        __half* pa = As + stg * HTSZ;
        __half* pb = Bs + stg * HTSZ;
#pragma unroll
        for (int i = 0; i < 2; i++) {
            int row = i * 64 + l_row;
            int gm = bm + row;
            int ok = (gm < M) ? 16 : 0;
            int gmc = min(gm, M - 1);
            cp_async16(pa + row * HASTR + l_chk, A + (size_t)gmc * K + k0 + l_chk, ok);
        }
#pragma unroll
        for (int i = 0; i < 2; i++) {
            int row = i * 64 + l_row;
            cp_async16(pb + row * HASTR + l_chk, Bt + (size_t)(bn + row) * K + k0 + l_chk, 16);
        }
    };

    const int nk = K / 32;
    load_stage(0, 0);
    asm volatile("cp.async.commit_group;");

    for (int tk = 0; tk < nk; tk++) {
        if (tk + 1 < nk) {
            load_stage((tk + 1) & 1, (tk + 1) * 32);
            asm volatile("cp.async.commit_group;");
            asm volatile("cp.async.wait_group 1;");
        } else {
            asm volatile("cp.async.wait_group 0;");
        }
        __syncthreads();

        const __half* pa = As + (tk & 1) * HTSZ;
        const __half* pb = Bs + (tk & 1) * HTSZ;
#pragma unroll
        for (int kk = 0; kk < 32; kk += 16) {
            uint32_t afrag[2][4];
            uint32_t bfrag[8][2];
#pragma unroll
            for (int im = 0; im < 2; im++) {
                const __half* base = pa + (warpM * 32 + im * 16 + g) * HASTR + kk + 2 * t;
                afrag[im][0] = *(const uint32_t*)(base);
                afrag[im][1] = *(const uint32_t*)(base + 8 * HASTR);
                afrag[im][2] = *(const uint32_t*)(base + 8);
                afrag[im][3] = *(const uint32_t*)(base + 8 * HASTR + 8);
            }
#pragma unroll
            for (int jn = 0; jn < 8; jn++) {
                const __half* base = pb + (warpN * 64 + jn * 8 + g) * HASTR + kk + 2 * t;
                bfrag[jn][0] = *(const uint32_t*)(base);
                bfrag[jn][1] = *(const uint32_t*)(base + 8);
            }
#pragma unroll
            for (int im = 0; im < 2; im++)
#pragma unroll
                for (int jn = 0; jn < 8; jn++) {
                    float4& c = acc[im][jn];
                    asm volatile(
                        "mma.sync.aligned.m16n8k16.row.col.f32.f16.f16.f32 "
                        "{%0,%1,%2,%3}, {%4,%5,%6,%7}, {%8,%9}, {%0,%1,%2,%3};"
                        : "+f"(c.x), "+f"(c.y), "+f"(c.z), "+f"(c.w)
                        : "r"(afrag[im][0]), "r"(afrag[im][1]),
                          "r"(afrag[im][2]), "r"(afrag[im][3]),
                          "r"(bfrag[jn][0]), "r"(bfrag[jn][1]));
                }
        }
        __syncthreads();
    }

#pragma unroll
    for (int jn = 0; jn < 8; jn++) {
        int col = bn + warpN * 64 + jn * 8 + 2 * t;
        float bx = bias[col], by = bias[col + 1];
        float s0 = 0.f, q0 = 0.f, s1 = 0.f, q1 = 0.f;
#pragma unroll
        for (int im = 0; im < 2; im++) {
            int row0 = bm + warpM * 32 + im * 16 + g;
            float4 c = acc[im][jn];
            if (row0 < M) {
                float ox = c.x + bx, oy = c.y + by;
                *(uint32_t*)(C + (size_t)row0 * N + col) = pack_h2(ox, oy);
                s0 += ox; q0 += ox * ox; s1 += oy; q1 += oy * oy;
            }
            if (row0 + 8 < M) {
                float oz = c.z + bx, ow = c.w + by;
                *(uint32_t*)(C + (size_t)(row0 + 8) * N + col) = pack_h2(oz, ow);
                s0 += oz; q0 += oz * oz; s1 += ow; q1 += ow * ow;
            }
        }
#pragma unroll
        for (int m = 4; m < 32; m <<= 1) {
            s0 += __shfl_xor_sync(0xffffffffu, s0, m);
            q0 += __shfl_xor_sync(0xffffffffu, q0, m);
            s1 += __shfl_xor_sync(0xffffffffu, s1, m);
            q1 += __shfl_xor_sync(0xffffffffu, q1, m);
        }
        if (g == 0) {
            red_add_v2(&stats[col], s0, q0);
            red_add_v2(&stats[col + 1], s1, q1);
        }
    }
}

// ---------------------------------------------------------------------------
// Final fp16 GEMM: A = raw fp16 h2, BN2+ReLU applied at frag build,
// B = fp16 Wl^T. Output fp32. Same pipeline shape.
// ---------------------------------------------------------------------------
__global__ __launch_bounds__(256) void k_gemm_finh(const __half* __restrict__ A,
                                                   const __half* __restrict__ Bt,
                                                   const float* __restrict__ bias,
                                                   float* __restrict__ C,
                                                   const float2* __restrict__ ssA,
                                                   int M, int N, int K) {
    extern __shared__ __half smh[];
    __half* As = smh;
    __half* Bs = smh + 2 * HTSZ;
    float2* ssm = (float2*)(smh + 4 * HTSZ);

    const int tid  = threadIdx.x;
    const int lane = tid & 31;
    const int warpId = tid >> 5;
    const int warpM = warpId & 3;
    const int warpN = warpId >> 2;
    const int g = lane >> 2;
    const int t = lane & 3;
    const int bm = blockIdx.y * GBM;
    const int bn = blockIdx.x * GBN;

    for (int c = tid; c < K; c += 256) ssm[c] = ssA[c];

    const int l_row = tid >> 2;
    const int l_chk = (tid & 3) * 8;

    float4 acc[2][8];
#pragma unroll
    for (int i = 0; i < 2; i++)
#pragma unroll
        for (int j = 0; j < 8; j++)
            acc[i][j] = make_float4(0.f, 0.f, 0.f, 0.f);

    auto load_stage = [&](int stg, int k0) {
        __half* pa = As + stg * HTSZ;
        __half* pb = Bs + stg * HTSZ;
#pragma unroll
        for (int i = 0; i < 2; i++) {
            int row = i * 64 + l_row;
            int gm = bm + row;
            int ok = (gm < M) ? 16 : 0;
            int gmc = min(gm, M - 1);
            cp_async16(pa + row * HASTR + l_chk, A + (size_t)gmc * K + k0 + l_chk, ok);
        }
#pragma unroll
        for (int i = 0; i < 2; i++) {
            int row = i * 64 + l_row;
            cp_async16(pb + row * HASTR + l_chk, Bt + (size_t)(bn + row) * K + k0 + l_chk, 16);
        }
    };

    const int nk = K / 32;
    load_stage(0, 0);
    asm volatile("cp.async.commit_group;");

    for (int tk = 0; tk < nk; tk++) {
        if (tk + 1 < nk) {
            load_stage((tk + 1) & 1, (tk + 1) * 32);
            asm volatile("cp.async.commit_group;");
            asm volatile("cp.async.wait_group 1;");
        } else {
            asm volatile("cp.async.wait_group 0;");
        }
        __syncthreads();

        const __half* pa = As + (tk & 1) * HTSZ;
        const __half* pb = Bs + (tk & 1) * HTSZ;
        const int kbase = tk * 32;
#pragma unroll
        for (int kk = 0; kk < 32; kk += 16) {
            int kc = kbase + kk + 2 * t;
            float2 s0 = ssm[kc],     s1 = ssm[kc + 1];
            float2 s2 = ssm[kc + 8], s3 = ssm[kc + 9];
            uint32_t afrag[2][4];
            uint32_t bfrag[8][2];
#pragma unroll
            for (int im = 0; im < 2; im++) {
                const __half* base = pa + (warpM * 32 + im * 16 + g) * HASTR + kk + 2 * t;
                float2 f0 = unpack_h2(*(const uint32_t*)(base));
                float2 f1 = unpack_h2(*(const uint32_t*)(base + 8 * HASTR));
                float2 f2 = unpack_h2(*(const uint32_t*)(base + 8));
                float2 f3 = unpack_h2(*(const uint32_t*)(base + 8 * HASTR + 8));
                afrag[im][0] = pack_h2(fmaxf(fmaf(f0.x, s0.x, s0.y), 0.f),
                                       fmaxf(fmaf(f0.y, s1.x, s1.y), 0.f));
                afrag[im][1] = pack_h2(fmaxf(fmaf(f1.x, s0.x, s0.y), 0.f),
                                       fmaxf(fmaf(f1.y, s1.x, s1.y), 0.f));
                afrag[im][2] = pack_h2(fmaxf(fmaf(f2.x, s2.x, s2.y), 0.f),
                                       fmaxf(fmaf(f2.y, s3.x, s3.y), 0.f));
                afrag[im][3] = pack_h2(fmaxf(fmaf(f3.x, s2.x, s2.y), 0.f),
                                       fmaxf(fmaf(f3.y, s3.x, s3.y), 0.f));
            }
#pragma unroll
            for (int jn = 0; jn < 8; jn++) {
                const __half* base = pb + (warpN * 64 + jn * 8 + g) * HASTR + kk + 2 * t;
                bfrag[jn][0] = *(const uint32_t*)(base);
                bfrag[jn][1] = *(const uint32_t*)(base + 8);
            }
#pragma unroll
            for (int im = 0; im < 2; im++)
#pragma unroll
                for (int jn = 0; jn < 8; jn++) {
                    float4& c = acc[im][jn];
                    asm volatile(
                        "mma.sync.aligned.m16n8k16.row.col.f32.f16.f16.f32 "
                        "{%0,%1,%2,%3}, {%4,%5,%6,%7}, {%8,%9}, {%0,%1,%2,%3};"
                        : "+f"(c.x), "+f"(c.y), "+f"(c.z), "+f"(c.w)
                        : "r"(afrag[im][0]), "r"(afrag[im][1]),
                          "r"(afrag[im][2]), "r"(afrag[im][3]),
                          "r"(bfrag[jn][0]), "r"(bfrag[jn][1]));
                }
        }
        __syncthreads();
    }

#pragma unroll
    for (int jn = 0; jn < 8; jn++) {
        int col = bn + warpN * 64 + jn * 8 + 2 * t;
        float bx = bias[col], by = bias[col + 1];
#pragma unroll
        for (int im = 0; im < 2; im++) {
            int row0 = bm + warpM * 32 + im * 16 + g;
            float4 c = acc[im][jn];
            if (row0 < M)
                *(float2*)(C + (size_t)row0 * N + col) = make_float2(c.x + bx, c.y + by);
            if (row0 + 8 < M)
                *(float2*)(C + (size_t)(row0 + 8) * N + col) = make_float2(c.z + bx, c.w + by);
        }
    }
}

// --- stats -> per-col (scale, shift) ------------------------------------------
__global__ void k_bnprep(const float2* __restrict__ stats,
                         const float* __restrict__ gamma,
                         const float* __restrict__ beta,
                         float2* __restrict__ ss, int D, float invM) {
    int c = blockIdx.x * blockDim.x + threadIdx.x;
    if (c < D) {
        float mu = stats[c].x * invM;
        float var = stats[c].y * invM - mu * mu;
        float sc = gamma[c] * rsqrtf(var + EPS);
        ss[c] = make_float2(sc, beta[c] - mu * sc);
    }
}

// ---------------------------------------------------------------------------

extern "C" void kernel_launch(void* const* d_in, const int* in_sizes, int n_in,
                              void* d_out, int out_size) {
    const float* x      = (const float*)d_in[0];
    const void*  ei     = d_in[1];
    const float* W1     = (const float*)d_in[2];
    const float* b1     = (const float*)d_in[3];
    const float* gamma1 = (const float*)d_in[4];
    const float* beta1  = (const float*)d_in[5];
    const float* W2     = (const float*)d_in[6];
    const float* b2     = (const float*)d_in[7];
    const float* gamma2 = (const float*)d_in[8];
    const float* beta2  = (const float*)d_in[9];
    const float* Wl     = (const float*)d_in[10];
    const float* bl     = (const float*)d_in[11];

    const int H1   = in_sizes[3];               // 256
    const int H2   = in_sizes[7];               // 512
    const int DOUT = in_sizes[11];              // 128
    const int DIN  = in_sizes[2] / H1;          // 128
    const int N    = in_sizes[0] / DIN;         // 50000
    const long long E = in_sizes[1] / 2;        // 500000
    const float invM = 1.0f / (float)N;

    float *dinv;
    __half *agg1h, *agg2h, *h1, *h2, *w1t, *w2t, *wlt;
    float2 *stats1, *stats2, *ss1, *ss2;
    int *cnt, *rowptr, *cursor, *flag, *bsum;
    int2* adj;
    cudaGetSymbolAddress((void**)&dinv,   g_dinv);
    cudaGetSymbolAddress((void**)&cnt,    g_cnt);
    cudaGetSymbolAddress((void**)&rowptr, g_rowptr);
    cudaGetSymbolAddress((void**)&cursor, g_cursor);
    cudaGetSymbolAddress((void**)&bsum,   g_bsum);
    cudaGetSymbolAddress((void**)&adj,    g_adj);
    cudaGetSymbolAddress((void**)&agg1h,  g_agg1h);
    cudaGetSymbolAddress((void**)&agg2h,  g_agg2h);
    cudaGetSymbolAddress((void**)&h1,     g_h1);
    cudaGetSymbolAddress((void**)&h2,     g_h2);
    cudaGetSymbolAddress((void**)&w1t,    g_w1t);
    cudaGetSymbolAddress((void**)&w2t,    g_w2t);
    cudaGetSymbolAddress((void**)&wlt,    g_wlt);
    cudaGetSymbolAddress((void**)&stats1, g_stats1);
    cudaGetSymbolAddress((void**)&stats2, g_stats2);
    cudaGetSymbolAddress((void**)&ss1,    g_ss1);
    cudaGetSymbolAddress((void**)&ss2,    g_ss2);
    cudaGetSymbolAddress((void**)&flag,   g_flag32);

    float* out = (float*)d_out;

    cudaFuncSetAttribute(k_gemm_h,    cudaFuncAttributeMaxDynamicSharedMemorySize, SMEM_H);
    cudaFuncSetAttribute(k_gemm_finh, cudaFuncAttributeMaxDynamicSharedMemorySize, SMEM_FINH);

    const int scanBlocks = (N + SCAN_BLK - 1) / SCAN_BLK;
    const int aggBlocks = (int)(((long long)N * 32 + 255) / 256);

    // prep (5 launches) -> agg1 is launch #6 (ncu -s 5 -c 1 profiles it)
    k_prep0<<<(N + 255) / 256, 256>>>((const int*)ei, E, cnt, N, stats1, stats2, H1, H2, flag);
    k_count<<<1024, 256>>>(ei, E, flag, cnt);
    k_scan_red<<<scanBlocks, SCAN_BLK>>>(cnt, bsum, N);
    k_scan_apply<<<scanBlocks, SCAN_BLK>>>(cnt, bsum, scanBlocks, rowptr, cursor, dinv, N);
    k_fill<<<1024, 256>>>(ei, E, flag, dinv, cursor, adj);

    // layer 1 aggregation (launch #6)
    k_agg1<<<aggBlocks, 256>>>(adj, rowptr, dinv, x, agg1h, N);

    // weight conversion (independent of agg)
    k_cvtw<<<(H1 * H2 + 255) / 256, 256>>>(W1, W2, Wl, w1t, w2t, wlt,
                                           DIN, H1, H1, H2, H2, DOUT);

    // layer 1 GEMM + BN prep
    {
        dim3 grid(H1 / GBN, (N + GBM - 1) / GBM);
        k_gemm_h<<<grid, 256, SMEM_H>>>(agg1h, w1t, b1, h1, stats1, N, H1, DIN);
        k_bnprep<<<(H1 + 255) / 256, 256>>>(stats1, gamma1, beta1, ss1, H1, invM);
    }

    // layer 2
    k_agg2<<<aggBlocks, 256>>>(adj, rowptr, dinv, h1, agg2h, N, ss1);
    {
        dim3 grid(H2 / GBN, (N + GBM - 1) / GBM);
        k_gemm_h<<<grid, 256, SMEM_H>>>(agg2h, w2t, b2, h2, stats2, N, H2, H1);
        k_bnprep<<<(H2 + 255) / 256, 256>>>(stats2, gamma2, beta2, ss2, H2, invM);
    }

    // final projection
    {
        dim3 grid(DOUT / GBN, (N + GBM - 1) / GBM);
        k_gemm_finh<<<grid, 256, SMEM_FINH>>>(h2, wlt, bl, out, ss2, N, DOUT, H2);
    }
}